// round 9
// baseline (speedup 1.0000x reference)
#include <cuda_runtime.h>
#include <cuda_bf16.h>

#define NB   16
#define NA   8400
#define NCLS 80
#define PRE  1000
#define KEEP 100

// ---------------- global scratch (stage-A outputs only) ------------------
static __device__ float4        g_box[NB * NA];
static __device__ unsigned      g_key[NB * NA];
static __device__ unsigned char g_lab[NB * NA];

// ---------------- XLA-exact sigmoid -------------------------------------
// XLA logistic expander: logistic(x) = 0.5 + 0.5 * tanh(0.5 * x)
// XLA fast-tanh: clamp [-9,9], rational poly, identity for |x| < 0.0004.
__device__ __forceinline__ float xla_fast_tanh(float x) {
    float ax = fabsf(x);
    float xc = fminf(fmaxf(x, -9.0f), 9.0f);
    float x2 = __fmul_rn(xc, xc);
    float num = -2.76076847742355e-16f;
    num = __fadd_rn(__fmul_rn(x2, num), 2.00018790482477e-13f);
    num = __fadd_rn(__fmul_rn(x2, num), -8.60467152213735e-11f);
    num = __fadd_rn(__fmul_rn(x2, num), 5.12229709037114e-08f);
    num = __fadd_rn(__fmul_rn(x2, num), 1.48572235717979e-05f);
    num = __fadd_rn(__fmul_rn(x2, num), 6.37261928875436e-04f);
    num = __fadd_rn(__fmul_rn(x2, num), 4.89352455891786e-03f);
    num = __fmul_rn(xc, num);
    float den = 1.19825839466702e-06f;
    den = __fadd_rn(__fmul_rn(x2, den), 1.18534705686654e-04f);
    den = __fadd_rn(__fmul_rn(x2, den), 2.26843463243900e-03f);
    den = __fadd_rn(__fmul_rn(x2, den), 4.89352518554385e-03f);
    float r = __fdiv_rn(num, den);
    return (ax < 0.0004f) ? x : r;
}
__device__ __forceinline__ float xla_sigmoid(float x) {
    return __fadd_rn(0.5f, __fmul_rn(0.5f, xla_fast_tanh(__fmul_rn(0.5f, x))));
}

// ---------------- stage A: pair-split classes, top-2 logit tracking -----
// Thread pair (even/odd lane neighbors) splits the 80 classes 40/40; merge
// top-2 via shuffles. Even's classes are all < odd's, so strict compares
// reproduce first-occurrence (smallest-label) tie semantics exactly.
// max(sigmoid)=sigmoid(max logit) when runner-up >= 1e-3 below; near-ties
// evaluate both sigmoids with reference tie-breaking.
__global__ void __launch_bounds__(256) k_score(
        const float* __restrict__ cls0, const float* __restrict__ cls1,
        const float* __restrict__ cls2, const float* __restrict__ box0,
        const float* __restrict__ box1, const float* __restrict__ box2) {
    int t   = blockIdx.x * 256 + threadIdx.x;
    int g   = t >> 1;               // anchor-group of 4 anchors
    int half = t & 1;               // 0: classes 0-39, 1: classes 40-79
    int b   = blockIdx.y;
    bool wok = (g < NA / 4);
    int gg = wok ? g : (NA / 4 - 1);

    const float4* cp4; const float4* bp4;
    int hw4, W, lp, abase; float sf;
    if (gg < 1600)      { lp = gg;        hw4 = 1600; W = 80; sf = 8.0f;  abase = 0;
                          cp4 = (const float4*)cls0 + (size_t)b * NCLS * 1600;
                          bp4 = (const float4*)box0 + (size_t)b * 4 * 1600; }
    else if (gg < 2000) { lp = gg - 1600; hw4 = 400;  W = 40; sf = 16.0f; abase = 6400;
                          cp4 = (const float4*)cls1 + (size_t)b * NCLS * 400;
                          bp4 = (const float4*)box1 + (size_t)b * 4 * 400; }
    else                { lp = gg - 2000; hw4 = 100;  W = 20; sf = 32.0f; abase = 8000;
                          cp4 = (const float4*)cls2 + (size_t)b * NCLS * 100;
                          bp4 = (const float4*)box2 + (size_t)b * 4 * 100; }

    float best[4], best2[4];
    int   lab[4],  lab2[4];
    #pragma unroll
    for (int j = 0; j < 4; j++) { best[j] = -1e30f; best2[j] = -1e30f; lab[j] = 0; lab2[j] = 0; }

    int c0 = half * 40;
    #pragma unroll 8
    for (int cc = 0; cc < 40; cc++) {
        int c = c0 + cc;
        float4 v = cp4[(size_t)c * hw4 + lp];
        float xs[4] = {v.x, v.y, v.z, v.w};
        #pragma unroll
        for (int j = 0; j < 4; j++) {
            float x = xs[j];
            if (x > best[j])       { best2[j] = best[j]; lab2[j] = lab[j]; best[j] = x; lab[j] = c; }
            else if (x > best2[j]) { best2[j] = x; lab2[j] = c; }
        }
    }

    int base4 = (b * NA + abase) / 4 + lp;

    // merge halves (all threads shuffle; even thread consumes)
    float ob[4], ob2[4]; int ol[4], ol2[4];
    #pragma unroll
    for (int j = 0; j < 4; j++) {
        ob[j]  = __shfl_xor_sync(0xffffffffu, best[j], 1);
        ob2[j] = __shfl_xor_sync(0xffffffffu, best2[j], 1);
        ol[j]  = __shfl_xor_sync(0xffffffffu, lab[j], 1);
        ol2[j] = __shfl_xor_sync(0xffffffffu, lab2[j], 1);
    }

    if (half == 0 && wok) {
        float score4[4]; unsigned key4[4]; unsigned char lab4[4];
        #pragma unroll
        for (int j = 0; j < 4; j++) {
            // merge top-2: even labels (<40) < odd labels; strict > keeps
            // the smaller label on equal values (first-occurrence).
            float B, S; int BL, SL;
            if (ob[j] > best[j]) {
                B = ob[j]; BL = ol[j];
                if (ob2[j] > best[j]) { S = ob2[j]; SL = ol2[j]; }
                else                  { S = best[j]; SL = lab[j]; }
            } else {
                B = best[j]; BL = lab[j];
                if (ob[j] > best2[j]) { S = ob[j]; SL = ol[j]; }
                else                  { S = best2[j]; SL = lab2[j]; }
            }
            float s1 = xla_sigmoid(B);
            float sc = s1; int lb = BL;
            if (__fsub_rn(B, S) < 1e-3f) {                 // rare near-tie
                float s2 = xla_sigmoid(S);
                if (s2 > s1 || (s2 == s1 && SL < lb)) { sc = s2; lb = SL; }
            }
            float masked = (sc > 0.25f) ? sc : 0.0f;
            score4[j] = masked;
            key4[j]   = __float_as_uint(masked) | 0x80000000u;
            lab4[j]   = (unsigned char)lb;
        }
        (void)score4;
        ((uint4*)g_key)[base4] = make_uint4(key4[0], key4[1], key4[2], key4[3]);
        *(uchar4*)(g_lab + (size_t)base4 * 4) = make_uchar4(lab4[0], lab4[1], lab4[2], lab4[3]);
    }
    if (half == 1 && wok) {
        float4 d0 = bp4[lp], d1 = bp4[hw4 + lp], d2 = bp4[2 * hw4 + lp], d3 = bp4[3 * hw4 + lp];
        float dd0[4] = {d0.x, d0.y, d0.z, d0.w};
        float dd1[4] = {d1.x, d1.y, d1.z, d1.w};
        float dd2[4] = {d2.x, d2.y, d2.z, d2.w};
        float dd3[4] = {d3.x, d3.y, d3.z, d3.w};
        #pragma unroll
        for (int j = 0; j < 4; j++) {
            int localj = lp * 4 + j;
            float px = __fmul_rn((float)(localj % W), sf);
            float py = __fmul_rn((float)(localj / W), sf);
            float e0 = __fmul_rn(dd0[j], sf);
            float e1 = __fmul_rn(dd1[j], sf);
            float e2 = __fmul_rn(dd2[j], sf);
            float e3 = __fmul_rn(dd3[j], sf);
            g_box[base4 * 4 + j] = make_float4(__fsub_rn(px, e0), __fsub_rn(py, e1),
                                               __fadd_rn(px, e2), __fadd_rn(py, e3));
        }
    }
}

// ---------------- fused stage B+C: top-1000 select + NMS + emit ----------
__global__ void __launch_bounds__(1024) k_sel_nms(float* __restrict__ dout) {
    __shared__ __align__(16) unsigned long long ssort[2048];   // sort + swap
    __shared__ __align__(16) float4 sbox[PRE];
    __shared__ float  sarea[PRE];
    __shared__ int    slabel[PRE];
    __shared__ int    slist[PRE];
    __shared__ unsigned char ssupp[PRE];
    __shared__ unsigned long long s_cnt64[32];
    __shared__ int s_n;
    __shared__ int sstart[NCLS + 1];
    __shared__ int scnt_[NCLS];
    __shared__ int swarp[32];

    int b = blockIdx.x, tid = threadIdx.x;
    int wid = tid >> 5, lane = tid & 31;

    // keys resident in registers for the whole search
    unsigned kreg[9];
    #pragma unroll
    for (int s = 0; s < 9; s++) {
        int i = tid + s * 1024;
        kreg[s] = (i < NA) ? g_key[b * NA + i] : 0u;
    }
    if (tid < 32) s_cnt64[tid] = 0ULL;
    if (tid == 0) s_n = 0;
    __syncthreads();

    // 4-way search: largest v with count(key >= v) >= PRE.  keys live in
    // [0x80000000, 0xBF800000); one barrier/iter via iteration slots.
    unsigned lo = 0x80000000u, hi = 0xBF7FFFFFu;
    int it = 0;
    while (hi - lo >= 4u) {
        unsigned q = (hi - lo) >> 2;
        unsigned m1 = lo + q, m2 = m1 + q, m3 = m2 + q;
        unsigned long long pc = 0ULL;
        #pragma unroll
        for (int s = 0; s < 9; s++) {
            unsigned k = kreg[s];
            pc += (unsigned long long)(k >= m1)
                + ((unsigned long long)(k >= m2) << 21)
                + ((unsigned long long)(k >= m3) << 42);
        }
        for (int d = 16; d; d >>= 1) pc += __shfl_down_sync(0xffffffffu, pc, d);
        if (lane == 0 && pc) atomicAdd(&s_cnt64[it & 31], pc);
        __syncthreads();
        unsigned long long t = s_cnt64[it & 31];
        unsigned c1 = (unsigned)(t & 0x1FFFFFu);
        unsigned c2 = (unsigned)((t >> 21) & 0x1FFFFFu);
        unsigned c3 = (unsigned)(t >> 42);
        if      (c3 >= PRE) lo = m3;
        else if (c2 >= PRE) { lo = m2; hi = m3 - 1u; }
        else if (c1 >= PRE) { lo = m1; hi = m2 - 1u; }
        else                hi = m1 - 1u;
        it++;
    }
    while (lo < hi) {                        // <=2 classic tail steps
        unsigned mid = lo + ((hi - lo) >> 1) + 1u;
        unsigned long long pc = 0ULL;
        #pragma unroll
        for (int s = 0; s < 9; s++) pc += (unsigned long long)(kreg[s] >= mid);
        for (int d = 16; d; d >>= 1) pc += __shfl_down_sync(0xffffffffu, pc, d);
        if (lane == 0 && pc) atomicAdd(&s_cnt64[it & 31], pc);
        __syncthreads();
        unsigned c1 = (unsigned)(s_cnt64[it & 31] & 0x1FFFFFu);
        if (c1 >= PRE) lo = mid; else hi = mid - 1u;
        it++;
    }
    unsigned v = lo;

    // gather: payload = key<<32 | (8399-idx)<<7 | label  (idx asc on key tie)
    #pragma unroll
    for (int s = 0; s < 9; s++) {
        unsigned k = kreg[s];
        if (k >= v) {
            int i = tid + s * 1024;
            int pos = atomicAdd(&s_n, 1);
            if (pos < 2048)
                ssort[pos] = ((unsigned long long)k << 32)
                           | ((unsigned)(8399 - i) << 7)
                           | (unsigned)g_lab[b * NA + i];
        }
    }
    __syncthreads();
    int n = s_n; if (n > 2048) n = 2048;

    unsigned long long val;
    if (n <= 1024) {
        // register bitonic, descending; shfl for j<=16, shared for j>=32
        val = (tid < n) ? ssort[tid] : 0ULL;
        __syncthreads();
        for (int k = 2; k <= 1024; k <<= 1) {
            for (int j = k >> 1; j > 0; j >>= 1) {
                unsigned long long partner;
                if (j >= 32) {
                    ssort[tid] = val;
                    __syncthreads();
                    partner = ssort[tid ^ j];
                    __syncthreads();
                } else {
                    partner = __shfl_xor_sync(0xffffffffu, val, j);
                }
                bool keep_max = ((tid & j) == 0) != ((tid & k) != 0);
                bool pgt = partner > val;
                if (keep_max == pgt) val = partner;
            }
        }
    } else {
        // rare fallback: in-shared 2048 bitonic
        for (int i = tid; i < 2048; i += 1024)
            if (i >= n) ssort[i] = 0ULL;
        __syncthreads();
        for (int k = 2; k <= 2048; k <<= 1) {
            for (int j = k >> 1; j > 0; j >>= 1) {
                for (int i = tid; i < 2048; i += 1024) {
                    int ixj = i ^ j;
                    if (ixj > i) {
                        unsigned long long x = ssort[i], y = ssort[ixj];
                        bool desc = ((i & k) == 0);
                        if ((x < y) == desc) { ssort[i] = y; ssort[ixj] = x; }
                    }
                }
                __syncthreads();
            }
        }
        val = ssort[tid];
        __syncthreads();
    }

    // decode own candidate (score recovered from key bits; one box load)
    float4 myraw = make_float4(0, 0, 0, 0);
    float  mysc = 0.0f; int mylab = 0;
    float4 myoff = myraw; float myarea = 0.0f;
    if (tid < PRE) {
        unsigned low = (unsigned)val;
        mylab = (int)(low & 0x7Fu);
        int idx = 8399 - (int)(low >> 7);
        mysc = __uint_as_float((unsigned)(val >> 32) & 0x7FFFFFFFu);
        myraw = g_box[b * NA + idx];
        float off = __fmul_rn((float)mylab, 8192.0f);
        myoff = make_float4(__fadd_rn(myraw.x, off), __fadd_rn(myraw.y, off),
                            __fadd_rn(myraw.z, off), __fadd_rn(myraw.w, off));
        myarea = __fmul_rn(fmaxf(__fsub_rn(myoff.z, myoff.x), 0.0f),
                           fmaxf(__fsub_rn(myoff.w, myoff.y), 0.0f));
        sbox[tid]   = myoff;
        sarea[tid]  = myarea;
        slabel[tid] = mylab;
        ssupp[tid]  = (mysc > 0.25f) ? 0 : 1;   // invalid = pre-suppressed
    }
    __syncthreads();

    // per-class counts via warp ballots (order-independent)
    for (int c = wid; c < NCLS; c += 32) {
        int cnt = 0;
        for (int base = 0; base < PRE; base += 32) {
            int i = base + lane;
            bool m = (i < PRE) && (slabel[i] == c);
            cnt += __popc(__ballot_sync(0xffffffffu, m));
        }
        if (lane == 0) scnt_[c] = cnt;
    }
    __syncthreads();

    // exclusive prefix over 80 class counts: warp 0 shfl-scan, 3 chunks
    if (wid == 0) {
        int carry = 0;
        #pragma unroll
        for (int chunk = 0; chunk < 3; chunk++) {
            int ci = chunk * 32 + lane;
            int x0 = (ci < NCLS) ? scnt_[ci] : 0;
            int x = x0;
            for (int d = 1; d < 32; d <<= 1) {
                int tt = __shfl_up_sync(0xffffffffu, x, d);
                if (lane >= d) x += tt;
            }
            if (ci < NCLS) sstart[ci] = carry + x - x0;
            carry += __shfl_sync(0xffffffffu, x, 31);
        }
        if (lane == 0) sstart[NCLS] = carry;
    }
    __syncthreads();

    // order-preserving scatter into per-class lists via ballots
    for (int c = wid; c < NCLS; c += 32) {
        int p = sstart[c];
        for (int base = 0; base < PRE; base += 32) {
            int i = base + lane;
            bool m = (i < PRE) && (slabel[i] == c);
            unsigned bal = __ballot_sync(0xffffffffu, m);
            if (m) slist[p + __popc(bal & ((1u << lane) - 1u))] = i;
            p += __popc(bal);
        }
    }
    __syncthreads();

    // one warp per class; greedy NMS, reference-exact IoU arithmetic.
    // cross-class IoU is exactly 0 (8192 class offset), so classes decouple.
    for (int c = wid; c < NCLS; c += 32) {
        int st = sstart[c], ni = sstart[c + 1] - st;
        for (int ii = 0; ii < ni; ii++) {
            __syncwarp();
            int idx_i = slist[st + ii];
            if (ssupp[idx_i]) continue;
            float4 bi = sbox[idx_i];
            float  ai = sarea[idx_i];
            for (int jj = ii + 1 + lane; jj < ni; jj += 32) {
                int idx_j = slist[st + jj];
                float4 bj = sbox[idx_j];
                float ltx = fmaxf(bi.x, bj.x), lty = fmaxf(bi.y, bj.y);
                float rbx = fminf(bi.z, bj.z), rby = fminf(bi.w, bj.w);
                float w = fmaxf(__fsub_rn(rbx, ltx), 0.0f);
                float h = fmaxf(__fsub_rn(rby, lty), 0.0f);
                float inter = __fmul_rn(w, h);
                float den = fmaxf(__fsub_rn(__fadd_rn(ai, sarea[idx_j]), inter), 1e-6f);
                if (__fdiv_rn(inter, den) > 0.65f) ssupp[idx_j] = 1;
            }
        }
        __syncwarp();
    }
    __syncthreads();

    // emit: kept entries keep sorted order; zero-score fills index-ascending
    bool keep = (tid < PRE) ? (ssupp[tid] == 0) : false;
    unsigned bal = __ballot_sync(0xffffffffu, keep);
    int before_in_warp = __popc(bal & ((1u << lane) - 1u));
    if (lane == 0) swarp[wid] = __popc(bal);
    __syncthreads();
    if (tid < 32) {
        int vv = swarp[tid];
        for (int d = 1; d < 32; d <<= 1) {
            int tt = __shfl_up_sync(0xffffffffu, vv, d);
            if (lane >= d) vv += tt;
        }
        swarp[tid] = vv;
    }
    __syncthreads();
    int rank = ((wid == 0) ? 0 : swarp[wid - 1]) + before_in_warp;
    int K = swarp[31];

    if (tid < PRE) {
        int slot = keep ? rank : (K + (tid - rank));
        if (slot < KEEP) {
            float* dd = dout + (size_t)b * KEEP * 5 + (size_t)slot * 5;
            float sc = keep ? mysc : 0.0f;
            dd[0] = myraw.x; dd[1] = myraw.y; dd[2] = myraw.z; dd[3] = myraw.w; dd[4] = sc;
            dout[(size_t)NB * KEEP * 5 + b * KEEP + slot] = (float)mylab;
        }
    }
}

extern "C" void kernel_launch(void* const* d_in, const int* in_sizes, int n_in,
                              void* d_out, int out_size) {
    const float* cls0 = (const float*)d_in[0];
    const float* cls1 = (const float*)d_in[1];
    const float* cls2 = (const float*)d_in[2];
    const float* box0 = (const float*)d_in[3];
    const float* box1 = (const float*)d_in[4];
    const float* box2 = (const float*)d_in[5];
    float* out = (float*)d_out;

    dim3 gA((NA / 4 * 2 + 255) / 256, NB);   // 17 x 16 blocks, thread-pairs
    k_score<<<gA, 256>>>(cls0, cls1, cls2, box0, box1, box2);
    k_sel_nms<<<NB, 1024>>>(out);
}

// round 10
// speedup vs baseline: 1.3207x; 1.3207x over previous
#include <cuda_runtime.h>
#include <cuda_bf16.h>

#define NB   16
#define NA   8400
#define NCLS 80
#define PRE  1000
#define KEEP 100
#define HBASE 0xBE800000u   // key base for score==0.25; valid keys are > this

// ---------------- global scratch ----------------------------------------
static __device__ float4        g_box[NB * NA];
static __device__ unsigned      g_key[NB * NA];
static __device__ unsigned char g_lab[NB * NA];
static __device__ int           g_hist[NB * 1024];   // zero-init; k_sel re-zeros

// key -> monotone bucket in [0,1023]
__device__ __forceinline__ unsigned key_bucket(unsigned k) {
    if (k <= HBASE) return 0u;
    unsigned u = (k - (HBASE + 1u)) >> 14;
    return 1u + (u > 1022u ? 1022u : u);
}

// ---------------- XLA-exact sigmoid -------------------------------------
// XLA logistic expander: logistic(x) = 0.5 + 0.5 * tanh(0.5 * x)
// XLA fast-tanh: clamp [-9,9], rational poly, identity for |x| < 0.0004.
__device__ __forceinline__ float xla_fast_tanh(float x) {
    float ax = fabsf(x);
    float xc = fminf(fmaxf(x, -9.0f), 9.0f);
    float x2 = __fmul_rn(xc, xc);
    float num = -2.76076847742355e-16f;
    num = __fadd_rn(__fmul_rn(x2, num), 2.00018790482477e-13f);
    num = __fadd_rn(__fmul_rn(x2, num), -8.60467152213735e-11f);
    num = __fadd_rn(__fmul_rn(x2, num), 5.12229709037114e-08f);
    num = __fadd_rn(__fmul_rn(x2, num), 1.48572235717979e-05f);
    num = __fadd_rn(__fmul_rn(x2, num), 6.37261928875436e-04f);
    num = __fadd_rn(__fmul_rn(x2, num), 4.89352455891786e-03f);
    num = __fmul_rn(xc, num);
    float den = 1.19825839466702e-06f;
    den = __fadd_rn(__fmul_rn(x2, den), 1.18534705686654e-04f);
    den = __fadd_rn(__fmul_rn(x2, den), 2.26843463243900e-03f);
    den = __fadd_rn(__fmul_rn(x2, den), 4.89352518554385e-03f);
    float r = __fdiv_rn(num, den);
    return (ax < 0.0004f) ? x : r;
}
__device__ __forceinline__ float xla_sigmoid(float x) {
    return __fadd_rn(0.5f, __fmul_rn(0.5f, xla_fast_tanh(__fmul_rn(0.5f, x))));
}

// ---------------- stage A: pair-split classes, top-2 logit tracking -----
__global__ void __launch_bounds__(256) k_score(
        const float* __restrict__ cls0, const float* __restrict__ cls1,
        const float* __restrict__ cls2, const float* __restrict__ box0,
        const float* __restrict__ box1, const float* __restrict__ box2) {
    int t   = blockIdx.x * 256 + threadIdx.x;
    int g   = t >> 1;               // anchor-group of 4 anchors
    int half = t & 1;               // 0: classes 0-39, 1: classes 40-79
    int b   = blockIdx.y;
    bool wok = (g < NA / 4);
    int gg = wok ? g : (NA / 4 - 1);

    const float4* cp4; const float4* bp4;
    int hw4, W, lp, abase; float sf;
    if (gg < 1600)      { lp = gg;        hw4 = 1600; W = 80; sf = 8.0f;  abase = 0;
                          cp4 = (const float4*)cls0 + (size_t)b * NCLS * 1600;
                          bp4 = (const float4*)box0 + (size_t)b * 4 * 1600; }
    else if (gg < 2000) { lp = gg - 1600; hw4 = 400;  W = 40; sf = 16.0f; abase = 6400;
                          cp4 = (const float4*)cls1 + (size_t)b * NCLS * 400;
                          bp4 = (const float4*)box1 + (size_t)b * 4 * 400; }
    else                { lp = gg - 2000; hw4 = 100;  W = 20; sf = 32.0f; abase = 8000;
                          cp4 = (const float4*)cls2 + (size_t)b * NCLS * 100;
                          bp4 = (const float4*)box2 + (size_t)b * 4 * 100; }

    float best[4], best2[4];
    int   lab[4],  lab2[4];
    #pragma unroll
    for (int j = 0; j < 4; j++) { best[j] = -1e30f; best2[j] = -1e30f; lab[j] = 0; lab2[j] = 0; }

    int c0 = half * 40;
    #pragma unroll 8
    for (int cc = 0; cc < 40; cc++) {
        int c = c0 + cc;
        float4 v = cp4[(size_t)c * hw4 + lp];
        float xs[4] = {v.x, v.y, v.z, v.w};
        #pragma unroll
        for (int j = 0; j < 4; j++) {
            float x = xs[j];
            if (x > best[j])       { best2[j] = best[j]; lab2[j] = lab[j]; best[j] = x; lab[j] = c; }
            else if (x > best2[j]) { best2[j] = x; lab2[j] = c; }
        }
    }

    int base4 = (b * NA + abase) / 4 + lp;

    float ob[4], ob2[4]; int ol[4], ol2[4];
    #pragma unroll
    for (int j = 0; j < 4; j++) {
        ob[j]  = __shfl_xor_sync(0xffffffffu, best[j], 1);
        ob2[j] = __shfl_xor_sync(0xffffffffu, best2[j], 1);
        ol[j]  = __shfl_xor_sync(0xffffffffu, lab[j], 1);
        ol2[j] = __shfl_xor_sync(0xffffffffu, lab2[j], 1);
    }

    if (half == 0 && wok) {
        unsigned key4[4]; unsigned char lab4[4];
        #pragma unroll
        for (int j = 0; j < 4; j++) {
            // merge top-2: even labels (<40) < odd; strict > keeps the
            // smaller label on equal values (first-occurrence).
            float B, S; int BL, SL;
            if (ob[j] > best[j]) {
                B = ob[j]; BL = ol[j];
                if (ob2[j] > best[j]) { S = ob2[j]; SL = ol2[j]; }
                else                  { S = best[j]; SL = lab[j]; }
            } else {
                B = best[j]; BL = lab[j];
                if (ob[j] > best2[j]) { S = ob[j]; SL = ol[j]; }
                else                  { S = best2[j]; SL = lab2[j]; }
            }
            float s1 = xla_sigmoid(B);
            float sc = s1; int lb = BL;
            if (__fsub_rn(B, S) < 1e-3f) {                 // rare near-tie
                float s2 = xla_sigmoid(S);
                if (s2 > s1 || (s2 == s1 && SL < lb)) { sc = s2; lb = SL; }
            }
            float masked = (sc > 0.25f) ? sc : 0.0f;
            key4[j] = __float_as_uint(masked) | 0x80000000u;
            lab4[j] = (unsigned char)lb;
            atomicAdd(&g_hist[b * 1024 + key_bucket(key4[j])], 1);
        }
        ((uint4*)g_key)[base4] = make_uint4(key4[0], key4[1], key4[2], key4[3]);
        *(uchar4*)(g_lab + (size_t)base4 * 4) = make_uchar4(lab4[0], lab4[1], lab4[2], lab4[3]);
    }
    if (half == 1 && wok) {
        float4 d0 = bp4[lp], d1 = bp4[hw4 + lp], d2 = bp4[2 * hw4 + lp], d3 = bp4[3 * hw4 + lp];
        float dd0[4] = {d0.x, d0.y, d0.z, d0.w};
        float dd1[4] = {d1.x, d1.y, d1.z, d1.w};
        float dd2[4] = {d2.x, d2.y, d2.z, d2.w};
        float dd3[4] = {d3.x, d3.y, d3.z, d3.w};
        #pragma unroll
        for (int j = 0; j < 4; j++) {
            int localj = lp * 4 + j;
            float px = __fmul_rn((float)(localj % W), sf);
            float py = __fmul_rn((float)(localj / W), sf);
            float e0 = __fmul_rn(dd0[j], sf);
            float e1 = __fmul_rn(dd1[j], sf);
            float e2 = __fmul_rn(dd2[j], sf);
            float e3 = __fmul_rn(dd3[j], sf);
            g_box[base4 * 4 + j] = make_float4(__fsub_rn(px, e0), __fsub_rn(py, e1),
                                               __fadd_rn(px, e2), __fadd_rn(py, e3));
        }
    }
}

// ---------------- fused stage B+C ---------------------------------------
__global__ void __launch_bounds__(1024) k_sel_nms(float* __restrict__ dout) {
    __shared__ __align__(16) unsigned long long ssort[2048];   // sort / scan alias
    __shared__ __align__(16) float4 sbox[PRE];
    __shared__ float  sarea[PRE];
    __shared__ int    slabel[PRE];
    __shared__ int    slist[PRE];
    __shared__ unsigned char ssupp[PRE];
    __shared__ int    swarp[32];
    __shared__ int    s_n, sT, sChi, sSv;
    __shared__ int    sstart[NCLS + 1];
    __shared__ int    scnt_[NCLS];

    int* sS = (int*)ssort;            // [1024] scan buffer (alias, pre-sort)
    int* h2 = (int*)ssort + 1024;     // [256]  sub-histogram (alias)

    int b = blockIdx.x, tid = threadIdx.x;
    int wid = tid >> 5, lane = tid & 31;

    // keys resident in registers
    unsigned kreg[9];
    #pragma unroll
    for (int s = 0; s < 9; s++) {
        int i = tid + s * 1024;
        kreg[s] = (i < NA) ? g_key[b * NA + i] : 0u;
    }

    // histogram: load + re-zero for next graph replay
    int hv = g_hist[b * 1024 + tid];
    g_hist[b * 1024 + tid] = 0;
    if (tid == 0) { s_n = 0; sT = -1; sChi = 0; sSv = 0; }

    // suffix scan over 1024 buckets (thread tid owns bucket 1023-tid)
    {
        int x = hv;    // value of bucket (1023 - tid) ... reindexed below
        // reindex: we want sS[tid] = sum of buckets (1023-tid)..1023
        // so thread tid should scan value of bucket 1023-tid: swap via shared
        sS[1023 - tid] = hv;
    }
    __syncthreads();
    {
        int x0 = sS[tid];             // bucket (1023 - tid)
        int x = x0;
        for (int d = 1; d < 32; d <<= 1) {
            int t2 = __shfl_up_sync(0xffffffffu, x, d);
            if (lane >= d) x += t2;
        }
        if (lane == 31) swarp[wid] = x;
        __syncthreads();
        if (wid == 0) {
            int v2 = swarp[lane];
            for (int d = 1; d < 32; d <<= 1) {
                int t2 = __shfl_up_sync(0xffffffffu, v2, d);
                if (lane >= d) v2 += t2;
            }
            swarp[lane] = v2;
        }
        __syncthreads();
        int incl = x + (wid ? swarp[wid - 1] : 0);
        __syncthreads();              // swarp reads done
        sS[tid] = incl;
        __syncthreads();
        if (incl >= PRE && (tid == 0 || sS[tid - 1] < PRE)) {
            sT = 1023 - tid;
            sChi = tid ? sS[tid - 1] : 0;
        }
        __syncthreads();
    }
    int T = sT, Chi = sChi;
    unsigned v;

    if (T >= 1 && T <= 1022) {
        // refine within bucket T: 256 sub-buckets of 64 key-values
        if (tid < 256) h2[tid] = 0;
        __syncthreads();
        #pragma unroll
        for (int s = 0; s < 9; s++) {
            unsigned k = kreg[s];
            if (key_bucket(k) == (unsigned)T)
                atomicAdd(&h2[((k - (HBASE + 1u)) >> 6) & 0xFFu], 1);
        }
        __syncthreads();
        // 256-wide suffix scan (warps 0-7)
        int x0 = 0, incl = 0;
        if (tid < 256) x0 = h2[255 - tid];
        int x = x0;
        for (int d = 1; d < 32; d <<= 1) {
            int t2 = __shfl_up_sync(0xffffffffu, x, d);
            if (lane >= d) x += t2;
        }
        if (tid < 256 && lane == 31) swarp[wid] = x;
        __syncthreads();
        if (wid == 0 && lane < 8) {
            int v2 = swarp[lane];
            for (int d = 1; d < 8; d <<= 1) {
                int t2 = __shfl_up_sync(0xFFu, v2, d);
                if (lane >= d) v2 += t2;
            }
            swarp[lane] = v2;
        }
        __syncthreads();
        if (tid < 256) incl = x + (wid ? swarp[wid - 1] : 0);
        __syncthreads();
        if (tid < 256) sS[tid] = incl;
        __syncthreads();
        int m = PRE - Chi;
        if (tid < 256 && incl >= m && (tid == 0 || sS[tid - 1] < m))
            sSv = 255 - tid;
        __syncthreads();
        v = (HBASE + 1u) + ((unsigned)(T - 1) << 14) + ((unsigned)sSv << 6);
    } else {
        // rare exact fallback: binary search on register keys
        if (tid < 32) swarp[tid] = 0;
        __syncthreads();
        unsigned lo = 0x80000000u, hi = 0xBF800000u;
        int it = 0;
        while (lo < hi) {
            unsigned mid = lo + ((hi - lo) >> 1) + 1u;
            int c = 0;
            #pragma unroll
            for (int s = 0; s < 9; s++) c += (kreg[s] >= mid);
            for (int d = 16; d; d >>= 1) c += __shfl_down_sync(0xffffffffu, c, d);
            if (lane == 0 && c) atomicAdd(&swarp[it & 31], c);
            __syncthreads();
            int total = swarp[it & 31];
            if (lane == 0) { }        // keep slot; next iter uses a new one
            if (total >= PRE) lo = mid; else hi = mid - 1u;
            it++;
            if ((it & 31) == 0) {     // recycle slots
                __syncthreads();
                if (tid < 32) swarp[tid] = 0;
                __syncthreads();
            }
        }
        v = lo;
    }
    __syncthreads();                  // sS/h2 dead -> ssort reusable

    // gather: payload = key<<32 | (8399-idx)<<7 | label  (idx asc on tie)
    #pragma unroll
    for (int s = 0; s < 9; s++) {
        unsigned k = kreg[s];
        if (k >= v) {
            int i = tid + s * 1024;
            int pos = atomicAdd(&s_n, 1);
            if (pos < 2048)
                ssort[pos] = ((unsigned long long)k << 32)
                           | ((unsigned)(8399 - i) << 7)
                           | (unsigned)g_lab[b * NA + i];
        }
    }
    __syncthreads();
    int n = s_n; if (n > 2048) n = 2048;
    int npow = (n <= 1024) ? 1024 : 2048;
    for (int i = tid; i < npow; i += 1024)
        if (i >= n) ssort[i] = 0ULL;
    __syncthreads();

    // shared bitonic sort, descending
    for (int k = 2; k <= npow; k <<= 1) {
        for (int j = k >> 1; j > 0; j >>= 1) {
            for (int i = tid; i < npow; i += 1024) {
                int ixj = i ^ j;
                if (ixj > i) {
                    unsigned long long x = ssort[i], y = ssort[ixj];
                    bool desc = ((i & k) == 0);
                    if ((x < y) == desc) { ssort[i] = y; ssort[ixj] = x; }
                }
            }
            __syncthreads();
        }
    }

    // decode own candidate (score from key bits; one scattered box load)
    float4 myraw = make_float4(0, 0, 0, 0);
    float  mysc = 0.0f; int mylab = 0;
    if (tid < PRE) {
        unsigned long long val = ssort[tid];
        unsigned low = (unsigned)val;
        mylab = (int)(low & 0x7Fu);
        int idx = 8399 - (int)((low >> 7) & 0x3FFFu);
        mysc = __uint_as_float((unsigned)(val >> 32) & 0x7FFFFFFFu);
        myraw = g_box[b * NA + idx];
        float off = __fmul_rn((float)mylab, 8192.0f);
        float4 myoff = make_float4(__fadd_rn(myraw.x, off), __fadd_rn(myraw.y, off),
                                   __fadd_rn(myraw.z, off), __fadd_rn(myraw.w, off));
        float myarea = __fmul_rn(fmaxf(__fsub_rn(myoff.z, myoff.x), 0.0f),
                                 fmaxf(__fsub_rn(myoff.w, myoff.y), 0.0f));
        sbox[tid]   = myoff;
        sarea[tid]  = myarea;
        slabel[tid] = mylab;
        ssupp[tid]  = (mysc > 0.25f) ? 0 : 1;   // invalid = pre-suppressed
    }
    __syncthreads();

    // per-class counts via warp ballots
    for (int c = wid; c < NCLS; c += 32) {
        int cnt = 0;
        for (int base = 0; base < PRE; base += 32) {
            int i = base + lane;
            bool m = (i < PRE) && (slabel[i] == c);
            cnt += __popc(__ballot_sync(0xffffffffu, m));
        }
        if (lane == 0) scnt_[c] = cnt;
    }
    __syncthreads();

    // exclusive prefix over 80 class counts: warp 0 shfl-scan, 3 chunks
    if (wid == 0) {
        int carry = 0;
        #pragma unroll
        for (int chunk = 0; chunk < 3; chunk++) {
            int ci = chunk * 32 + lane;
            int x0 = (ci < NCLS) ? scnt_[ci] : 0;
            int x = x0;
            for (int d = 1; d < 32; d <<= 1) {
                int tt = __shfl_up_sync(0xffffffffu, x, d);
                if (lane >= d) x += tt;
            }
            if (ci < NCLS) sstart[ci] = carry + x - x0;
            carry += __shfl_sync(0xffffffffu, x, 31);
        }
        if (lane == 0) sstart[NCLS] = carry;
    }
    __syncthreads();

    // order-preserving scatter into per-class lists
    for (int c = wid; c < NCLS; c += 32) {
        int p = sstart[c];
        for (int base = 0; base < PRE; base += 32) {
            int i = base + lane;
            bool m = (i < PRE) && (slabel[i] == c);
            unsigned bal = __ballot_sync(0xffffffffu, m);
            if (m) slist[p + __popc(bal & ((1u << lane) - 1u))] = i;
            p += __popc(bal);
        }
    }
    __syncthreads();

    // one warp per class; greedy NMS, reference-exact IoU arithmetic.
    // cross-class IoU is exactly 0 (8192 class offset), so classes decouple.
    for (int c = wid; c < NCLS; c += 32) {
        int st = sstart[c], ni = sstart[c + 1] - st;
        for (int ii = 0; ii < ni; ii++) {
            __syncwarp();
            int idx_i = slist[st + ii];
            if (ssupp[idx_i]) continue;
            float4 bi = sbox[idx_i];
            float  ai = sarea[idx_i];
            for (int jj = ii + 1 + lane; jj < ni; jj += 32) {
                int idx_j = slist[st + jj];
                float4 bj = sbox[idx_j];
                float ltx = fmaxf(bi.x, bj.x), lty = fmaxf(bi.y, bj.y);
                float rbx = fminf(bi.z, bj.z), rby = fminf(bi.w, bj.w);
                float w = fmaxf(__fsub_rn(rbx, ltx), 0.0f);
                float h = fmaxf(__fsub_rn(rby, lty), 0.0f);
                float inter = __fmul_rn(w, h);
                float den = fmaxf(__fsub_rn(__fadd_rn(ai, sarea[idx_j]), inter), 1e-6f);
                if (__fdiv_rn(inter, den) > 0.65f) ssupp[idx_j] = 1;
            }
        }
        __syncwarp();
    }
    __syncthreads();

    // emit: kept entries keep sorted order; zero-score fills index-ascending
    bool keep = (tid < PRE) ? (ssupp[tid] == 0) : false;
    unsigned bal = __ballot_sync(0xffffffffu, keep);
    int before_in_warp = __popc(bal & ((1u << lane) - 1u));
    if (lane == 0) swarp[wid] = __popc(bal);
    __syncthreads();
    if (tid < 32) {
        int vv = swarp[tid];
        for (int d = 1; d < 32; d <<= 1) {
            int tt = __shfl_up_sync(0xffffffffu, vv, d);
            if (lane >= d) vv += tt;
        }
        swarp[tid] = vv;
    }
    __syncthreads();
    int rank = ((wid == 0) ? 0 : swarp[wid - 1]) + before_in_warp;
    int K = swarp[31];

    if (tid < PRE) {
        int slot = keep ? rank : (K + (tid - rank));
        if (slot < KEEP) {
            float* dd = dout + (size_t)b * KEEP * 5 + (size_t)slot * 5;
            float sc = keep ? mysc : 0.0f;
            dd[0] = myraw.x; dd[1] = myraw.y; dd[2] = myraw.z; dd[3] = myraw.w; dd[4] = sc;
            dout[(size_t)NB * KEEP * 5 + b * KEEP + slot] = (float)mylab;
        }
    }
}

extern "C" void kernel_launch(void* const* d_in, const int* in_sizes, int n_in,
                              void* d_out, int out_size) {
    const float* cls0 = (const float*)d_in[0];
    const float* cls1 = (const float*)d_in[1];
    const float* cls2 = (const float*)d_in[2];
    const float* box0 = (const float*)d_in[3];
    const float* box1 = (const float*)d_in[4];
    const float* box2 = (const float*)d_in[5];
    float* out = (float*)d_out;

    dim3 gA((NA / 4 * 2 + 255) / 256, NB);
    k_score<<<gA, 256>>>(cls0, cls1, cls2, box0, box1, box2);
    k_sel_nms<<<NB, 1024>>>(out);
}

// round 11
// speedup vs baseline: 1.6256x; 1.2309x over previous
#include <cuda_runtime.h>
#include <cuda_bf16.h>

#define NB   16
#define NA   8400
#define NCLS 80
#define PRE  1000
#define KEEP 100
#define HBASE 0xBE800000u   // key base for score==0.25; valid keys are > this

// ---------------- global scratch ----------------------------------------
static __device__ float4        g_box[NB * NA];
static __device__ unsigned      g_key[NB * NA];
static __device__ unsigned char g_lab[NB * NA];
static __device__ int           g_hist[NB * 1024];   // zero-init; k_sel re-zeros

// key -> monotone bucket in [0,1023]
__device__ __forceinline__ unsigned key_bucket(unsigned k) {
    if (k <= HBASE) return 0u;
    unsigned u = (k - (HBASE + 1u)) >> 14;
    return 1u + (u > 1022u ? 1022u : u);
}

// ---------------- XLA-exact sigmoid -------------------------------------
// XLA logistic expander: logistic(x) = 0.5 + 0.5 * tanh(0.5 * x)
// XLA fast-tanh: clamp [-9,9], rational poly, identity for |x| < 0.0004.
__device__ __forceinline__ float xla_fast_tanh(float x) {
    float ax = fabsf(x);
    float xc = fminf(fmaxf(x, -9.0f), 9.0f);
    float x2 = __fmul_rn(xc, xc);
    float num = -2.76076847742355e-16f;
    num = __fadd_rn(__fmul_rn(x2, num), 2.00018790482477e-13f);
    num = __fadd_rn(__fmul_rn(x2, num), -8.60467152213735e-11f);
    num = __fadd_rn(__fmul_rn(x2, num), 5.12229709037114e-08f);
    num = __fadd_rn(__fmul_rn(x2, num), 1.48572235717979e-05f);
    num = __fadd_rn(__fmul_rn(x2, num), 6.37261928875436e-04f);
    num = __fadd_rn(__fmul_rn(x2, num), 4.89352455891786e-03f);
    num = __fmul_rn(xc, num);
    float den = 1.19825839466702e-06f;
    den = __fadd_rn(__fmul_rn(x2, den), 1.18534705686654e-04f);
    den = __fadd_rn(__fmul_rn(x2, den), 2.26843463243900e-03f);
    den = __fadd_rn(__fmul_rn(x2, den), 4.89352518554385e-03f);
    float r = __fdiv_rn(num, den);
    return (ax < 0.0004f) ? x : r;
}
__device__ __forceinline__ float xla_sigmoid(float x) {
    return __fadd_rn(0.5f, __fmul_rn(0.5f, xla_fast_tanh(__fmul_rn(0.5f, x))));
}

// ---------------- stage A: pair-split classes, top-2 logit tracking -----
__global__ void __launch_bounds__(256) k_score(
        const float* __restrict__ cls0, const float* __restrict__ cls1,
        const float* __restrict__ cls2, const float* __restrict__ box0,
        const float* __restrict__ box1, const float* __restrict__ box2) {
    int t   = blockIdx.x * 256 + threadIdx.x;
    int g   = t >> 1;               // anchor-group of 4 anchors
    int half = t & 1;               // 0: classes 0-39, 1: classes 40-79
    int b   = blockIdx.y;
    bool wok = (g < NA / 4);
    int gg = wok ? g : (NA / 4 - 1);

    const float4* cp4; const float4* bp4;
    int hw4, W, lp, abase; float sf;
    if (gg < 1600)      { lp = gg;        hw4 = 1600; W = 80; sf = 8.0f;  abase = 0;
                          cp4 = (const float4*)cls0 + (size_t)b * NCLS * 1600;
                          bp4 = (const float4*)box0 + (size_t)b * 4 * 1600; }
    else if (gg < 2000) { lp = gg - 1600; hw4 = 400;  W = 40; sf = 16.0f; abase = 6400;
                          cp4 = (const float4*)cls1 + (size_t)b * NCLS * 400;
                          bp4 = (const float4*)box1 + (size_t)b * 4 * 400; }
    else                { lp = gg - 2000; hw4 = 100;  W = 20; sf = 32.0f; abase = 8000;
                          cp4 = (const float4*)cls2 + (size_t)b * NCLS * 100;
                          bp4 = (const float4*)box2 + (size_t)b * 4 * 100; }

    float best[4], best2[4];
    int   lab[4],  lab2[4];
    #pragma unroll
    for (int j = 0; j < 4; j++) { best[j] = -1e30f; best2[j] = -1e30f; lab[j] = 0; lab2[j] = 0; }

    int c0 = half * 40;
    #pragma unroll 8
    for (int cc = 0; cc < 40; cc++) {
        int c = c0 + cc;
        float4 v = cp4[(size_t)c * hw4 + lp];
        float xs[4] = {v.x, v.y, v.z, v.w};
        #pragma unroll
        for (int j = 0; j < 4; j++) {
            float x = xs[j];
            if (x > best[j])       { best2[j] = best[j]; lab2[j] = lab[j]; best[j] = x; lab[j] = c; }
            else if (x > best2[j]) { best2[j] = x; lab2[j] = c; }
        }
    }

    int base4 = (b * NA + abase) / 4 + lp;

    float ob[4], ob2[4]; int ol[4], ol2[4];
    #pragma unroll
    for (int j = 0; j < 4; j++) {
        ob[j]  = __shfl_xor_sync(0xffffffffu, best[j], 1);
        ob2[j] = __shfl_xor_sync(0xffffffffu, best2[j], 1);
        ol[j]  = __shfl_xor_sync(0xffffffffu, lab[j], 1);
        ol2[j] = __shfl_xor_sync(0xffffffffu, lab2[j], 1);
    }

    if (half == 0 && wok) {
        unsigned key4[4]; unsigned char lab4[4];
        #pragma unroll
        for (int j = 0; j < 4; j++) {
            // merge top-2: even labels (<40) < odd; strict > keeps the
            // smaller label on equal values (first-occurrence).
            float B, S; int BL, SL;
            if (ob[j] > best[j]) {
                B = ob[j]; BL = ol[j];
                if (ob2[j] > best[j]) { S = ob2[j]; SL = ol2[j]; }
                else                  { S = best[j]; SL = lab[j]; }
            } else {
                B = best[j]; BL = lab[j];
                if (ob[j] > best2[j]) { S = ob[j]; SL = ol[j]; }
                else                  { S = best2[j]; SL = lab2[j]; }
            }
            float s1 = xla_sigmoid(B);
            float sc = s1; int lb = BL;
            if (__fsub_rn(B, S) < 1e-3f) {                 // rare near-tie
                float s2 = xla_sigmoid(S);
                if (s2 > s1 || (s2 == s1 && SL < lb)) { sc = s2; lb = SL; }
            }
            float masked = (sc > 0.25f) ? sc : 0.0f;
            key4[j] = __float_as_uint(masked) | 0x80000000u;
            lab4[j] = (unsigned char)lb;
            atomicAdd(&g_hist[b * 1024 + key_bucket(key4[j])], 1);
        }
        ((uint4*)g_key)[base4] = make_uint4(key4[0], key4[1], key4[2], key4[3]);
        *(uchar4*)(g_lab + (size_t)base4 * 4) = make_uchar4(lab4[0], lab4[1], lab4[2], lab4[3]);
    }
    if (half == 1 && wok) {
        float4 d0 = bp4[lp], d1 = bp4[hw4 + lp], d2 = bp4[2 * hw4 + lp], d3 = bp4[3 * hw4 + lp];
        float dd0[4] = {d0.x, d0.y, d0.z, d0.w};
        float dd1[4] = {d1.x, d1.y, d1.z, d1.w};
        float dd2[4] = {d2.x, d2.y, d2.z, d2.w};
        float dd3[4] = {d3.x, d3.y, d3.z, d3.w};
        #pragma unroll
        for (int j = 0; j < 4; j++) {
            int localj = lp * 4 + j;
            float px = __fmul_rn((float)(localj % W), sf);
            float py = __fmul_rn((float)(localj / W), sf);
            float e0 = __fmul_rn(dd0[j], sf);
            float e1 = __fmul_rn(dd1[j], sf);
            float e2 = __fmul_rn(dd2[j], sf);
            float e3 = __fmul_rn(dd3[j], sf);
            g_box[base4 * 4 + j] = make_float4(__fsub_rn(px, e0), __fsub_rn(py, e1),
                                               __fadd_rn(px, e2), __fadd_rn(py, e3));
        }
    }
}

// ---------------- fused stage B+C ---------------------------------------
__global__ void __launch_bounds__(1024) k_sel_nms(float* __restrict__ dout) {
    __shared__ __align__(16) unsigned long long ssort[2048];   // sort / scan alias
    __shared__ __align__(16) float4 sbox[PRE];
    __shared__ float  sarea[PRE];
    __shared__ int    slist[PRE];
    __shared__ unsigned char ssupp[PRE];
    __shared__ int    swarp[32];
    __shared__ int    s_n, sT, sChi, sSv;
    __shared__ int    sstart[NCLS + 1];
    __shared__ int    scnt_[NCLS];
    __shared__ int    soff[NCLS];

    int* sS = (int*)ssort;            // [1024] scan buffer (alias, pre-sort)
    int* h2 = (int*)ssort + 1024;     // [256]  sub-histogram (alias)

    int b = blockIdx.x, tid = threadIdx.x;
    int wid = tid >> 5, lane = tid & 31;

    // keys resident in registers
    unsigned kreg[9];
    #pragma unroll
    for (int s = 0; s < 9; s++) {
        int i = tid + s * 1024;
        kreg[s] = (i < NA) ? g_key[b * NA + i] : 0u;
    }

    // histogram: load + re-zero for next graph replay
    int hv = g_hist[b * 1024 + tid];
    g_hist[b * 1024 + tid] = 0;
    if (tid == 0) { s_n = 0; sT = -1; sChi = 0; sSv = 0; }
    if (tid < NCLS) scnt_[tid] = 0;

    // suffix scan over 1024 buckets (thread tid owns bucket 1023-tid)
    sS[1023 - tid] = hv;
    __syncthreads();
    {
        int x0 = sS[tid];             // bucket (1023 - tid)
        int x = x0;
        for (int d = 1; d < 32; d <<= 1) {
            int t2 = __shfl_up_sync(0xffffffffu, x, d);
            if (lane >= d) x += t2;
        }
        if (lane == 31) swarp[wid] = x;
        __syncthreads();
        if (wid == 0) {
            int v2 = swarp[lane];
            for (int d = 1; d < 32; d <<= 1) {
                int t2 = __shfl_up_sync(0xffffffffu, v2, d);
                if (lane >= d) v2 += t2;
            }
            swarp[lane] = v2;
        }
        __syncthreads();
        int incl = x + (wid ? swarp[wid - 1] : 0);
        __syncthreads();              // swarp reads done
        sS[tid] = incl;
        __syncthreads();
        if (incl >= PRE && (tid == 0 || sS[tid - 1] < PRE)) {
            sT = 1023 - tid;
            sChi = tid ? sS[tid - 1] : 0;
        }
        __syncthreads();
    }
    int T = sT, Chi = sChi;
    unsigned v;

    if (T >= 1 && T <= 1022) {
        // refine within bucket T: 256 sub-buckets of 64 key-values
        if (tid < 256) h2[tid] = 0;
        __syncthreads();
        #pragma unroll
        for (int s = 0; s < 9; s++) {
            unsigned k = kreg[s];
            if (key_bucket(k) == (unsigned)T)
                atomicAdd(&h2[((k - (HBASE + 1u)) >> 6) & 0xFFu], 1);
        }
        __syncthreads();
        // 256-wide suffix scan (warps 0-7)
        int x0 = 0, incl = 0;
        if (tid < 256) x0 = h2[255 - tid];
        int x = x0;
        for (int d = 1; d < 32; d <<= 1) {
            int t2 = __shfl_up_sync(0xffffffffu, x, d);
            if (lane >= d) x += t2;
        }
        if (tid < 256 && lane == 31) swarp[wid] = x;
        __syncthreads();
        if (wid == 0 && lane < 8) {
            int v2 = swarp[lane];
            for (int d = 1; d < 8; d <<= 1) {
                int t2 = __shfl_up_sync(0xFFu, v2, d);
                if (lane >= d) v2 += t2;
            }
            swarp[lane] = v2;
        }
        __syncthreads();
        if (tid < 256) incl = x + (wid ? swarp[wid - 1] : 0);
        __syncthreads();
        if (tid < 256) sS[tid] = incl;
        __syncthreads();
        int m = PRE - Chi;
        if (tid < 256 && incl >= m && (tid == 0 || sS[tid - 1] < m))
            sSv = 255 - tid;
        __syncthreads();
        v = (HBASE + 1u) + ((unsigned)(T - 1) << 14) + ((unsigned)sSv << 6);
    } else {
        // rare exact fallback: binary search on register keys
        if (tid < 32) swarp[tid] = 0;
        __syncthreads();
        unsigned lo = 0x80000000u, hi = 0xBF800000u;
        int it = 0;
        while (lo < hi) {
            unsigned mid = lo + ((hi - lo) >> 1) + 1u;
            int c = 0;
            #pragma unroll
            for (int s = 0; s < 9; s++) c += (kreg[s] >= mid);
            for (int d = 16; d; d >>= 1) c += __shfl_down_sync(0xffffffffu, c, d);
            if (lane == 0 && c) atomicAdd(&swarp[it & 31], c);
            __syncthreads();
            int total = swarp[it & 31];
            if (total >= PRE) lo = mid; else hi = mid - 1u;
            it++;
            if ((it & 31) == 0) {
                __syncthreads();
                if (tid < 32) swarp[tid] = 0;
                __syncthreads();
            }
        }
        v = lo;
    }
    __syncthreads();                  // sS/h2 dead -> ssort reusable

    // gather: payload = key<<32 | (8399-idx)<<7 | label  (idx asc on tie)
    #pragma unroll
    for (int s = 0; s < 9; s++) {
        unsigned k = kreg[s];
        if (k >= v) {
            int i = tid + s * 1024;
            int pos = atomicAdd(&s_n, 1);
            if (pos < 2048)
                ssort[pos] = ((unsigned long long)k << 32)
                           | ((unsigned)(8399 - i) << 7)
                           | (unsigned)g_lab[b * NA + i];
        }
    }
    __syncthreads();
    int n = s_n; if (n > 2048) n = 2048;

    unsigned long long val;
    if (n <= 1024) {
        // hybrid bitonic, descending: registers + shfl for j<=16,
        // shared exchange for j>=32 (15 phases x 2 barriers).
        val = (tid < n) ? ssort[tid] : 0ULL;
        __syncthreads();
        for (int k = 2; k <= 1024; k <<= 1) {
            for (int j = k >> 1; j > 0; j >>= 1) {
                unsigned long long partner;
                if (j >= 32) {
                    ssort[tid] = val;
                    __syncthreads();
                    partner = ssort[tid ^ j];
                    __syncthreads();
                } else {
                    partner = __shfl_xor_sync(0xffffffffu, val, j);
                }
                bool keep_max = ((tid & j) == 0) != ((tid & k) != 0);
                bool pgt = partner > val;
                if (keep_max == pgt) val = partner;
            }
        }
    } else {
        // rare fallback: in-shared 2048 bitonic
        for (int i = tid; i < 2048; i += 1024)
            if (i >= n) ssort[i] = 0ULL;
        __syncthreads();
        for (int k = 2; k <= 2048; k <<= 1) {
            for (int j = k >> 1; j > 0; j >>= 1) {
                for (int i = tid; i < 2048; i += 1024) {
                    int ixj = i ^ j;
                    if (ixj > i) {
                        unsigned long long x = ssort[i], y = ssort[ixj];
                        bool desc = ((i & k) == 0);
                        if ((x < y) == desc) { ssort[i] = y; ssort[ixj] = x; }
                    }
                }
                __syncthreads();
            }
        }
        val = ssort[tid];
        __syncthreads();
    }

    // decode own candidate; count classes via one atomic each
    float4 myraw = make_float4(0, 0, 0, 0);
    float  mysc = 0.0f; int mylab = 0;
    if (tid < PRE) {
        unsigned low = (unsigned)val;
        mylab = (int)(low & 0x7Fu);
        int idx = 8399 - (int)((low >> 7) & 0x3FFFu);
        mysc = __uint_as_float((unsigned)(val >> 32) & 0x7FFFFFFFu);
        myraw = g_box[b * NA + idx];
        float off = __fmul_rn((float)mylab, 8192.0f);
        float4 myoff = make_float4(__fadd_rn(myraw.x, off), __fadd_rn(myraw.y, off),
                                   __fadd_rn(myraw.z, off), __fadd_rn(myraw.w, off));
        float myarea = __fmul_rn(fmaxf(__fsub_rn(myoff.z, myoff.x), 0.0f),
                                 fmaxf(__fsub_rn(myoff.w, myoff.y), 0.0f));
        sbox[tid]   = myoff;
        sarea[tid]  = myarea;
        ssupp[tid]  = (mysc > 0.25f) ? 0 : 1;   // invalid = pre-suppressed
        atomicAdd(&scnt_[mylab], 1);
    }
    __syncthreads();

    // exclusive prefix over 80 class counts: warp 0 shfl-scan, 3 chunks
    if (wid == 0) {
        int carry = 0;
        #pragma unroll
        for (int chunk = 0; chunk < 3; chunk++) {
            int ci = chunk * 32 + lane;
            int x0 = (ci < NCLS) ? scnt_[ci] : 0;
            int x = x0;
            for (int d = 1; d < 32; d <<= 1) {
                int tt = __shfl_up_sync(0xffffffffu, x, d);
                if (lane >= d) x += tt;
            }
            if (ci < NCLS) sstart[ci] = carry + x - x0;
            carry += __shfl_sync(0xffffffffu, x, 31);
        }
        if (lane == 0) sstart[NCLS] = carry;
    }
    __syncthreads();
    if (tid < NCLS) soff[tid] = sstart[tid];
    __syncthreads();

    // unordered scatter, then per-warp class-segment sort (positions asc)
    if (tid < PRE) slist[atomicAdd(&soff[mylab], 1)] = tid;
    __syncthreads();

    for (int c = wid; c < NCLS; c += 32) {
        int st = sstart[c], ni = sstart[c + 1] - st;
        if (ni > 1) {
            if (ni <= 32) {
                // in-warp bitonic descending on ~pos => ascending pos;
                // pad lanes get 0 (sinks past the valid region).
                unsigned vv = (lane < ni) ? ~(unsigned)slist[st + lane] : 0u;
                #pragma unroll
                for (int k = 2; k <= 32; k <<= 1) {
                    #pragma unroll
                    for (int j = k >> 1; j > 0; j >>= 1) {
                        unsigned p = __shfl_xor_sync(0xffffffffu, vv, j);
                        bool keep_max = ((lane & j) == 0) != ((lane & k) != 0);
                        if (keep_max == (p > vv)) vv = p;
                    }
                }
                if (lane < ni) slist[st + lane] = (int)~vv;
            } else if (lane == 0) {
                // astronomically rare: serial insertion sort (correctness net)
                for (int a2 = st + 1; a2 < st + ni; a2++) {
                    int x = slist[a2]; int bq = a2 - 1;
                    while (bq >= st && slist[bq] > x) { slist[bq + 1] = slist[bq]; bq--; }
                    slist[bq + 1] = x;
                }
            }
        }
        __syncwarp();
    }
    __syncthreads();

    // one warp per class; greedy NMS, reference-exact IoU arithmetic.
    // cross-class IoU is exactly 0 (8192 class offset), so classes decouple.
    for (int c = wid; c < NCLS; c += 32) {
        int st = sstart[c], ni = sstart[c + 1] - st;
        for (int ii = 0; ii < ni; ii++) {
            __syncwarp();
            int idx_i = slist[st + ii];
            if (ssupp[idx_i]) continue;
            float4 bi = sbox[idx_i];
            float  ai = sarea[idx_i];
            for (int jj = ii + 1 + lane; jj < ni; jj += 32) {
                int idx_j = slist[st + jj];
                float4 bj = sbox[idx_j];
                float ltx = fmaxf(bi.x, bj.x), lty = fmaxf(bi.y, bj.y);
                float rbx = fminf(bi.z, bj.z), rby = fminf(bi.w, bj.w);
                float w = fmaxf(__fsub_rn(rbx, ltx), 0.0f);
                float h = fmaxf(__fsub_rn(rby, lty), 0.0f);
                float inter = __fmul_rn(w, h);
                float den = fmaxf(__fsub_rn(__fadd_rn(ai, sarea[idx_j]), inter), 1e-6f);
                if (__fdiv_rn(inter, den) > 0.65f) ssupp[idx_j] = 1;
            }
        }
        __syncwarp();
    }
    __syncthreads();

    // emit: kept entries keep sorted order; zero-score fills index-ascending
    bool keep = (tid < PRE) ? (ssupp[tid] == 0) : false;
    unsigned bal = __ballot_sync(0xffffffffu, keep);
    int before_in_warp = __popc(bal & ((1u << lane) - 1u));
    if (lane == 0) swarp[wid] = __popc(bal);
    __syncthreads();
    if (tid < 32) {
        int vv = swarp[tid];
        for (int d = 1; d < 32; d <<= 1) {
            int tt = __shfl_up_sync(0xffffffffu, vv, d);
            if (lane >= d) vv += tt;
        }
        swarp[tid] = vv;
    }
    __syncthreads();
    int rank = ((wid == 0) ? 0 : swarp[wid - 1]) + before_in_warp;
    int K = swarp[31];

    if (tid < PRE) {
        int slot = keep ? rank : (K + (tid - rank));
        if (slot < KEEP) {
            float* dd = dout + (size_t)b * KEEP * 5 + (size_t)slot * 5;
            float sc = keep ? mysc : 0.0f;
            dd[0] = myraw.x; dd[1] = myraw.y; dd[2] = myraw.z; dd[3] = myraw.w; dd[4] = sc;
            dout[(size_t)NB * KEEP * 5 + b * KEEP + slot] = (float)mylab;
        }
    }
}

extern "C" void kernel_launch(void* const* d_in, const int* in_sizes, int n_in,
                              void* d_out, int out_size) {
    const float* cls0 = (const float*)d_in[0];
    const float* cls1 = (const float*)d_in[1];
    const float* cls2 = (const float*)d_in[2];
    const float* box0 = (const float*)d_in[3];
    const float* box1 = (const float*)d_in[4];
    const float* box2 = (const float*)d_in[5];
    float* out = (float*)d_out;

    dim3 gA((NA / 4 * 2 + 255) / 256, NB);
    k_score<<<gA, 256>>>(cls0, cls1, cls2, box0, box1, box2);
    k_sel_nms<<<NB, 1024>>>(out);
}

// round 14
// speedup vs baseline: 1.6266x; 1.0006x over previous
#include <cuda_runtime.h>
#include <cuda_bf16.h>

#define NB   16
#define NA   8400
#define NCLS 80
#define PRE  1000
#define KEEP 100
#define HBASE 0xBE800000u   // key base for score==0.25; valid keys are > this

// ---------------- global scratch ----------------------------------------
static __device__ float4        g_box[NB * NA];
static __device__ unsigned      g_key[NB * NA];
static __device__ unsigned char g_lab[NB * NA];
static __device__ int           g_hist[NB * 1024];   // zero-init; k_sel re-zeros

// key -> monotone bucket in [0,1023]
__device__ __forceinline__ unsigned key_bucket(unsigned k) {
    if (k <= HBASE) return 0u;
    unsigned u = (k - (HBASE + 1u)) >> 14;
    return 1u + (u > 1022u ? 1022u : u);
}

// ---------------- XLA-exact sigmoid -------------------------------------
// XLA logistic expander: logistic(x) = 0.5 + 0.5 * tanh(0.5 * x)
// XLA fast-tanh: clamp [-9,9], rational poly, identity for |x| < 0.0004.
__device__ __forceinline__ float xla_fast_tanh(float x) {
    float ax = fabsf(x);
    float xc = fminf(fmaxf(x, -9.0f), 9.0f);
    float x2 = __fmul_rn(xc, xc);
    float num = -2.76076847742355e-16f;
    num = __fadd_rn(__fmul_rn(x2, num), 2.00018790482477e-13f);
    num = __fadd_rn(__fmul_rn(x2, num), -8.60467152213735e-11f);
    num = __fadd_rn(__fmul_rn(x2, num), 5.12229709037114e-08f);
    num = __fadd_rn(__fmul_rn(x2, num), 1.48572235717979e-05f);
    num = __fadd_rn(__fmul_rn(x2, num), 6.37261928875436e-04f);
    num = __fadd_rn(__fmul_rn(x2, num), 4.89352455891786e-03f);
    num = __fmul_rn(xc, num);
    float den = 1.19825839466702e-06f;
    den = __fadd_rn(__fmul_rn(x2, den), 1.18534705686654e-04f);
    den = __fadd_rn(__fmul_rn(x2, den), 2.26843463243900e-03f);
    den = __fadd_rn(__fmul_rn(x2, den), 4.89352518554385e-03f);
    float r = __fdiv_rn(num, den);
    return (ax < 0.0004f) ? x : r;
}
__device__ __forceinline__ float xla_sigmoid(float x) {
    return __fadd_rn(0.5f, __fmul_rn(0.5f, xla_fast_tanh(__fmul_rn(0.5f, x))));
}

// ---------------- stage A: pair-split classes, top-2 logit tracking -----
__global__ void __launch_bounds__(256) k_score(
        const float* __restrict__ cls0, const float* __restrict__ cls1,
        const float* __restrict__ cls2, const float* __restrict__ box0,
        const float* __restrict__ box1, const float* __restrict__ box2) {
    int t   = blockIdx.x * 256 + threadIdx.x;
    int g   = t >> 1;               // anchor-group of 4 anchors
    int half = t & 1;               // 0: classes 0-39, 1: classes 40-79
    int b   = blockIdx.y;
    bool wok = (g < NA / 4);
    int gg = wok ? g : (NA / 4 - 1);

    const float4* cp4; const float4* bp4;
    int hw4, W, lp, abase; float sf;
    if (gg < 1600)      { lp = gg;        hw4 = 1600; W = 80; sf = 8.0f;  abase = 0;
                          cp4 = (const float4*)cls0 + (size_t)b * NCLS * 1600;
                          bp4 = (const float4*)box0 + (size_t)b * 4 * 1600; }
    else if (gg < 2000) { lp = gg - 1600; hw4 = 400;  W = 40; sf = 16.0f; abase = 6400;
                          cp4 = (const float4*)cls1 + (size_t)b * NCLS * 400;
                          bp4 = (const float4*)box1 + (size_t)b * 4 * 400; }
    else                { lp = gg - 2000; hw4 = 100;  W = 20; sf = 32.0f; abase = 8000;
                          cp4 = (const float4*)cls2 + (size_t)b * NCLS * 100;
                          bp4 = (const float4*)box2 + (size_t)b * 4 * 100; }

    float best[4], best2[4];
    int   lab[4],  lab2[4];
    #pragma unroll
    for (int j = 0; j < 4; j++) { best[j] = -1e30f; best2[j] = -1e30f; lab[j] = 0; lab2[j] = 0; }

    int c0 = half * 40;
    #pragma unroll 8
    for (int cc = 0; cc < 40; cc++) {
        int c = c0 + cc;
        float4 v = cp4[(size_t)c * hw4 + lp];
        float xs[4] = {v.x, v.y, v.z, v.w};
        #pragma unroll
        for (int j = 0; j < 4; j++) {
            float x = xs[j];
            if (x > best[j])       { best2[j] = best[j]; lab2[j] = lab[j]; best[j] = x; lab[j] = c; }
            else if (x > best2[j]) { best2[j] = x; lab2[j] = c; }
        }
    }

    int base4 = (b * NA + abase) / 4 + lp;

    float ob[4], ob2[4]; int ol[4], ol2[4];
    #pragma unroll
    for (int j = 0; j < 4; j++) {
        ob[j]  = __shfl_xor_sync(0xffffffffu, best[j], 1);
        ob2[j] = __shfl_xor_sync(0xffffffffu, best2[j], 1);
        ol[j]  = __shfl_xor_sync(0xffffffffu, lab[j], 1);
        ol2[j] = __shfl_xor_sync(0xffffffffu, lab2[j], 1);
    }

    if (half == 0 && wok) {
        unsigned key4[4]; unsigned char lab4[4];
        #pragma unroll
        for (int j = 0; j < 4; j++) {
            // merge top-2: even labels (<40) < odd; strict > keeps the
            // smaller label on equal values (first-occurrence).
            float B, S; int BL, SL;
            if (ob[j] > best[j]) {
                B = ob[j]; BL = ol[j];
                if (ob2[j] > best[j]) { S = ob2[j]; SL = ol2[j]; }
                else                  { S = best[j]; SL = lab[j]; }
            } else {
                B = best[j]; BL = lab[j];
                if (ob[j] > best2[j]) { S = ob[j]; SL = ol[j]; }
                else                  { S = best2[j]; SL = lab2[j]; }
            }
            float s1 = xla_sigmoid(B);
            float sc = s1; int lb = BL;
            if (__fsub_rn(B, S) < 1e-3f) {                 // rare near-tie
                float s2 = xla_sigmoid(S);
                if (s2 > s1 || (s2 == s1 && SL < lb)) { sc = s2; lb = SL; }
            }
            float masked = (sc > 0.25f) ? sc : 0.0f;
            key4[j] = __float_as_uint(masked) | 0x80000000u;
            lab4[j] = (unsigned char)lb;
            atomicAdd(&g_hist[b * 1024 + key_bucket(key4[j])], 1);
        }
        ((uint4*)g_key)[base4] = make_uint4(key4[0], key4[1], key4[2], key4[3]);
        *(uchar4*)(g_lab + (size_t)base4 * 4) = make_uchar4(lab4[0], lab4[1], lab4[2], lab4[3]);
    }
    if (half == 1 && wok) {
        float4 d0 = bp4[lp], d1 = bp4[hw4 + lp], d2 = bp4[2 * hw4 + lp], d3 = bp4[3 * hw4 + lp];
        float dd0[4] = {d0.x, d0.y, d0.z, d0.w};
        float dd1[4] = {d1.x, d1.y, d1.z, d1.w};
        float dd2[4] = {d2.x, d2.y, d2.z, d2.w};
        float dd3[4] = {d3.x, d3.y, d3.z, d3.w};
        #pragma unroll
        for (int j = 0; j < 4; j++) {
            int localj = lp * 4 + j;
            float px = __fmul_rn((float)(localj % W), sf);
            float py = __fmul_rn((float)(localj / W), sf);
            float e0 = __fmul_rn(dd0[j], sf);
            float e1 = __fmul_rn(dd1[j], sf);
            float e2 = __fmul_rn(dd2[j], sf);
            float e3 = __fmul_rn(dd3[j], sf);
            g_box[base4 * 4 + j] = make_float4(__fsub_rn(px, e0), __fsub_rn(py, e1),
                                               __fadd_rn(px, e2), __fadd_rn(py, e3));
        }
    }
}

// ---------------- fused stage B+C ---------------------------------------
__global__ void __launch_bounds__(1024) k_sel_nms(float* __restrict__ dout) {
    __shared__ __align__(16) unsigned long long ssort[2048];   // sorted / grp / scan alias
    __shared__ __align__(16) float4 sbox[PRE];                 // also hcand/hcursor/hscan
    __shared__ float  sarea[PRE];
    __shared__ int    slist[PRE];
    __shared__ unsigned char ssupp[PRE];
    __shared__ int    swarp[32];
    __shared__ int    s_n, sT, sChi, sSv;
    __shared__ int    sstart[NCLS + 1];
    __shared__ int    scnt_[NCLS];
    __shared__ int    soff[NCLS];

    int* sS = (int*)ssort;            // [1024] scan buffer (alias, pre-sort)
    int* h2 = (int*)ssort + 1024;     // [256]  sub-histogram (alias)
    int* hcand   = (int*)sbox;        // [1024] candidate bucket counts
    int* hcursor = (int*)sbox + 1024; // [1024] segment cursors / ends
    int* hscan   = (int*)sbox + 2048; // [1024] scan staging

    int b = blockIdx.x, tid = threadIdx.x;
    int wid = tid >> 5, lane = tid & 31;

    // keys resident in registers
    unsigned kreg[9];
    #pragma unroll
    for (int s = 0; s < 9; s++) {
        int i = tid + s * 1024;
        kreg[s] = (i < NA) ? g_key[b * NA + i] : 0u;
    }

    // histogram: load + re-zero for next graph replay
    int hv = g_hist[b * 1024 + tid];
    g_hist[b * 1024 + tid] = 0;
    if (tid == 0) { s_n = 0; sT = -1; sChi = 0; sSv = 0; }
    if (tid < NCLS) scnt_[tid] = 0;
    hcand[tid] = 0;

    // suffix scan over 1024 buckets (thread tid owns bucket 1023-tid)
    sS[1023 - tid] = hv;
    __syncthreads();
    {
        int x0 = sS[tid];             // bucket (1023 - tid)
        int x = x0;
        for (int d = 1; d < 32; d <<= 1) {
            int t2 = __shfl_up_sync(0xffffffffu, x, d);
            if (lane >= d) x += t2;
        }
        if (lane == 31) swarp[wid] = x;
        __syncthreads();
        if (wid == 0) {
            int v2 = swarp[lane];
            for (int d = 1; d < 32; d <<= 1) {
                int t2 = __shfl_up_sync(0xffffffffu, v2, d);
                if (lane >= d) v2 += t2;
            }
            swarp[lane] = v2;
        }
        __syncthreads();
        int incl = x + (wid ? swarp[wid - 1] : 0);
        __syncthreads();              // swarp reads done
        sS[tid] = incl;
        __syncthreads();
        if (incl >= PRE && (tid == 0 || sS[tid - 1] < PRE)) {
            sT = 1023 - tid;
            sChi = tid ? sS[tid - 1] : 0;
        }
        __syncthreads();
    }
    int T = sT, Chi = sChi;
    unsigned v;

    if (T >= 1 && T <= 1022) {
        // refine within bucket T: 256 sub-buckets of 64 key-values
        if (tid < 256) h2[tid] = 0;
        __syncthreads();
        #pragma unroll
        for (int s = 0; s < 9; s++) {
            unsigned k = kreg[s];
            if (key_bucket(k) == (unsigned)T)
                atomicAdd(&h2[((k - (HBASE + 1u)) >> 6) & 0xFFu], 1);
        }
        __syncthreads();
        // 256-wide suffix scan (warps 0-7)
        int x0 = 0, incl = 0;
        if (tid < 256) x0 = h2[255 - tid];
        int x = x0;
        for (int d = 1; d < 32; d <<= 1) {
            int t2 = __shfl_up_sync(0xffffffffu, x, d);
            if (lane >= d) x += t2;
        }
        if (tid < 256 && lane == 31) swarp[wid] = x;
        __syncthreads();
        if (wid == 0 && lane < 8) {
            int v2 = swarp[lane];
            for (int d = 1; d < 8; d <<= 1) {
                int t2 = __shfl_up_sync(0xFFu, v2, d);
                if (lane >= d) v2 += t2;
            }
            swarp[lane] = v2;
        }
        __syncthreads();
        if (tid < 256) incl = x + (wid ? swarp[wid - 1] : 0);
        __syncthreads();
        if (tid < 256) sS[tid] = incl;
        __syncthreads();
        int m = PRE - Chi;
        if (tid < 256 && incl >= m && (tid == 0 || sS[tid - 1] < m))
            sSv = 255 - tid;
        __syncthreads();
        v = (HBASE + 1u) + ((unsigned)(T - 1) << 14) + ((unsigned)sSv << 6);
    } else {
        // rare exact fallback: binary search on register keys
        if (tid < 32) swarp[tid] = 0;
        __syncthreads();
        unsigned lo = 0x80000000u, hi = 0xBF800000u;
        int it = 0;
        while (lo < hi) {
            unsigned mid = lo + ((hi - lo) >> 1) + 1u;
            int c = 0;
            #pragma unroll
            for (int s = 0; s < 9; s++) c += (kreg[s] >= mid);
            for (int d = 16; d; d >>= 1) c += __shfl_down_sync(0xffffffffu, c, d);
            if (lane == 0 && c) atomicAdd(&swarp[it & 31], c);
            __syncthreads();
            int total = swarp[it & 31];
            if (total >= PRE) lo = mid; else hi = mid - 1u;
            it++;
            if ((it & 31) == 0) {
                __syncthreads();
                if (tid < 32) swarp[tid] = 0;
                __syncthreads();
            }
        }
        v = lo;
    }
    __syncthreads();                  // sS/h2 dead -> ssort reusable

    // ---- counting sort replaces bitonic ----
    // pass 1: candidate bucket counts
    #pragma unroll
    for (int s = 0; s < 9; s++) {
        unsigned k = kreg[s];
        if (k >= v) atomicAdd(&hcand[key_bucket(k)], 1);
    }
    __syncthreads();

    // suffix scan of candidate buckets -> segment starts; total -> s_n
    hscan[1023 - tid] = hcand[tid];
    __syncthreads();
    {
        int x0 = hscan[tid];          // bucket (1023 - tid)
        int x = x0;
        for (int d = 1; d < 32; d <<= 1) {
            int t2 = __shfl_up_sync(0xffffffffu, x, d);
            if (lane >= d) x += t2;
        }
        if (lane == 31) swarp[wid] = x;
        __syncthreads();
        if (wid == 0) {
            int v2 = swarp[lane];
            for (int d = 1; d < 32; d <<= 1) {
                int t2 = __shfl_up_sync(0xffffffffu, v2, d);
                if (lane >= d) v2 += t2;
            }
            swarp[lane] = v2;
        }
        __syncthreads();
        int incl = x + (wid ? swarp[wid - 1] : 0);
        hcursor[1023 - tid] = incl - x0;      // exclusive suffix = segment start
        if (tid == 1023) s_n = incl;          // total candidates
        __syncthreads();
    }
    int n = s_n;

    unsigned long long val;
    if (n <= 1024) {
        unsigned long long* grp = ssort + 1024;
        // pass 2: scatter payloads into bucket segments (arbitrary order)
        #pragma unroll
        for (int s = 0; s < 9; s++) {
            unsigned k = kreg[s];
            if (k >= v) {
                int i = tid + s * 1024;
                unsigned long long pay = ((unsigned long long)k << 32)
                                       | ((unsigned)(8399 - i) << 7)
                                       | (unsigned)g_lab[b * NA + i];
                grp[atomicAdd(&hcursor[(int)key_bucket(k)], 1)] = pay;
            }
        }
        __syncthreads();
        // exact in-segment rank (payloads unique) -> direct placement
        if (tid < n) {
            unsigned long long pay = grp[tid];
            int t = (int)key_bucket((unsigned)(pay >> 32));
            int end = hcursor[t];             // post-scatter cursor = segment end
            int start = end - hcand[t];
            int rank = 0;
            for (int g2 = start; g2 < end; g2++) rank += (grp[g2] > pay);
            ssort[start + rank] = pay;
        }
        __syncthreads();
        val = (tid < n) ? ssort[tid] : 0ULL;
    } else {
        // pathological fallback: gather + 2048 bitonic
        if (tid == 0) sT = 0;
        __syncthreads();
        #pragma unroll
        for (int s = 0; s < 9; s++) {
            unsigned k = kreg[s];
            if (k >= v) {
                int i = tid + s * 1024;
                int pos = atomicAdd(&sT, 1);
                if (pos < 2048)
                    ssort[pos] = ((unsigned long long)k << 32)
                               | ((unsigned)(8399 - i) << 7)
                               | (unsigned)g_lab[b * NA + i];
            }
        }
        __syncthreads();
        int n2 = n > 2048 ? 2048 : n;
        for (int i = tid; i < 2048; i += 1024)
            if (i >= n2) ssort[i] = 0ULL;
        __syncthreads();
        for (int k = 2; k <= 2048; k <<= 1) {
            for (int j = k >> 1; j > 0; j >>= 1) {
                for (int i = tid; i < 2048; i += 1024) {
                    int ixj = i ^ j;
                    if (ixj > i) {
                        unsigned long long x = ssort[i], y = ssort[ixj];
                        bool desc = ((i & k) == 0);
                        if ((x < y) == desc) { ssort[i] = y; ssort[ixj] = x; }
                    }
                }
                __syncthreads();
            }
        }
        val = ssort[tid];
        __syncthreads();
    }

    // decode own candidate; count classes via one atomic each
    float4 myraw = make_float4(0, 0, 0, 0);
    float  mysc = 0.0f; int mylab = 0;
    if (tid < PRE) {
        unsigned low = (unsigned)val;
        mylab = (int)(low & 0x7Fu);
        int idx = 8399 - (int)((low >> 7) & 0x3FFFu);
        mysc = __uint_as_float((unsigned)(val >> 32) & 0x7FFFFFFFu);
        myraw = g_box[b * NA + idx];
        float off = __fmul_rn((float)mylab, 8192.0f);
        float4 myoff = make_float4(__fadd_rn(myraw.x, off), __fadd_rn(myraw.y, off),
                                   __fadd_rn(myraw.z, off), __fadd_rn(myraw.w, off));
        float myarea = __fmul_rn(fmaxf(__fsub_rn(myoff.z, myoff.x), 0.0f),
                                 fmaxf(__fsub_rn(myoff.w, myoff.y), 0.0f));
        sbox[tid]   = myoff;
        sarea[tid]  = myarea;
        ssupp[tid]  = (mysc > 0.25f) ? 0 : 1;   // invalid = pre-suppressed
        atomicAdd(&scnt_[mylab], 1);
    }
    __syncthreads();

    // exclusive prefix over 80 class counts: warp 0 shfl-scan, 3 chunks
    if (wid == 0) {
        int carry = 0;
        #pragma unroll
        for (int chunk = 0; chunk < 3; chunk++) {
            int ci = chunk * 32 + lane;
            int x0 = (ci < NCLS) ? scnt_[ci] : 0;
            int x = x0;
            for (int d = 1; d < 32; d <<= 1) {
                int tt = __shfl_up_sync(0xffffffffu, x, d);
                if (lane >= d) x += tt;
            }
            if (ci < NCLS) sstart[ci] = carry + x - x0;
            carry += __shfl_sync(0xffffffffu, x, 31);
        }
        if (lane == 0) sstart[NCLS] = carry;
    }
    __syncthreads();
    if (tid < NCLS) soff[tid] = sstart[tid];
    __syncthreads();

    // unordered scatter, then per-warp class-segment sort (positions asc)
    if (tid < PRE) slist[atomicAdd(&soff[mylab], 1)] = tid;
    __syncthreads();

    for (int c = wid; c < NCLS; c += 32) {
        int st = sstart[c], ni = sstart[c + 1] - st;
        if (ni > 1) {
            if (ni <= 32) {
                unsigned vv = (lane < ni) ? ~(unsigned)slist[st + lane] : 0u;
                #pragma unroll
                for (int k = 2; k <= 32; k <<= 1) {
                    #pragma unroll
                    for (int j = k >> 1; j > 0; j >>= 1) {
                        unsigned p = __shfl_xor_sync(0xffffffffu, vv, j);
                        bool keep_max = ((lane & j) == 0) != ((lane & k) != 0);
                        if (keep_max == (p > vv)) vv = p;
                    }
                }
                if (lane < ni) slist[st + lane] = (int)~vv;
            } else if (lane == 0) {
                for (int a2 = st + 1; a2 < st + ni; a2++) {
                    int x = slist[a2]; int bq = a2 - 1;
                    while (bq >= st && slist[bq] > x) { slist[bq + 1] = slist[bq]; bq--; }
                    slist[bq + 1] = x;
                }
            }
        }
        __syncwarp();
    }
    __syncthreads();

    // one warp per class; greedy NMS, reference-exact IoU arithmetic.
    // cross-class IoU is exactly 0 (8192 class offset), so classes decouple.
    for (int c = wid; c < NCLS; c += 32) {
        int st = sstart[c], ni = sstart[c + 1] - st;
        for (int ii = 0; ii < ni; ii++) {
            __syncwarp();
            int idx_i = slist[st + ii];
            if (ssupp[idx_i]) continue;
            float4 bi = sbox[idx_i];
            float  ai = sarea[idx_i];
            for (int jj = ii + 1 + lane; jj < ni; jj += 32) {
                int idx_j = slist[st + jj];
                float4 bj = sbox[idx_j];
                float ltx = fmaxf(bi.x, bj.x), lty = fmaxf(bi.y, bj.y);
                float rbx = fminf(bi.z, bj.z), rby = fminf(bi.w, bj.w);
                float w = fmaxf(__fsub_rn(rbx, ltx), 0.0f);
                float h = fmaxf(__fsub_rn(rby, lty), 0.0f);
                float inter = __fmul_rn(w, h);
                float den = fmaxf(__fsub_rn(__fadd_rn(ai, sarea[idx_j]), inter), 1e-6f);
                if (__fdiv_rn(inter, den) > 0.65f) ssupp[idx_j] = 1;
            }
        }
        __syncwarp();
    }
    __syncthreads();

    // emit: kept entries keep sorted order; zero-score fills index-ascending
    bool keep = (tid < PRE) ? (ssupp[tid] == 0) : false;
    unsigned bal = __ballot_sync(0xffffffffu, keep);
    int before_in_warp = __popc(bal & ((1u << lane) - 1u));
    if (lane == 0) swarp[wid] = __popc(bal);
    __syncthreads();
    if (tid < 32) {
        int vv = swarp[tid];
        for (int d = 1; d < 32; d <<= 1) {
            int tt = __shfl_up_sync(0xffffffffu, vv, d);
            if (lane >= d) vv += tt;
        }
        swarp[tid] = vv;
    }
    __syncthreads();
    int rank = ((wid == 0) ? 0 : swarp[wid - 1]) + before_in_warp;
    int K = swarp[31];

    if (tid < PRE) {
        int slot = keep ? rank : (K + (tid - rank));
        if (slot < KEEP) {
            float* dd = dout + (size_t)b * KEEP * 5 + (size_t)slot * 5;
            float sc = keep ? mysc : 0.0f;
            dd[0] = myraw.x; dd[1] = myraw.y; dd[2] = myraw.z; dd[3] = myraw.w; dd[4] = sc;
            dout[(size_t)NB * KEEP * 5 + b * KEEP + slot] = (float)mylab;
        }
    }
}

extern "C" void kernel_launch(void* const* d_in, const int* in_sizes, int n_in,
                              void* d_out, int out_size) {
    const float* cls0 = (const float*)d_in[0];
    const float* cls1 = (const float*)d_in[1];
    const float* cls2 = (const float*)d_in[2];
    const float* box0 = (const float*)d_in[3];
    const float* box1 = (const float*)d_in[4];
    const float* box2 = (const float*)d_in[5];
    float* out = (float*)d_out;

    dim3 gA((NA / 4 * 2 + 255) / 256, NB);
    k_score<<<gA, 256>>>(cls0, cls1, cls2, box0, box1, box2);
    k_sel_nms<<<NB, 1024>>>(out);
}

// round 15
// speedup vs baseline: 1.9298x; 1.1864x over previous
#include <cuda_runtime.h>
#include <cuda_bf16.h>

#define NB   16
#define NA   8400
#define NCLS 80
#define PRE  1000
#define KEEP 100
#define HBASE 0xBE800000u   // key base for score==0.25; valid keys are > this

// ---------------- global scratch ----------------------------------------
static __device__ float4        g_box[NB * NA];
static __device__ unsigned      g_key[NB * NA];
static __device__ unsigned char g_lab[NB * NA];
static __device__ int           g_hist[NB * 1024];   // zero-init; k_sel re-zeros

// key -> monotone bucket in [0,1023]
__device__ __forceinline__ unsigned key_bucket(unsigned k) {
    if (k <= HBASE) return 0u;
    unsigned u = (k - (HBASE + 1u)) >> 14;
    return 1u + (u > 1022u ? 1022u : u);
}

// ---------------- XLA-exact sigmoid -------------------------------------
// XLA logistic expander: logistic(x) = 0.5 + 0.5 * tanh(0.5 * x)
// XLA fast-tanh: clamp [-9,9], rational poly, identity for |x| < 0.0004.
__device__ __forceinline__ float xla_fast_tanh(float x) {
    float ax = fabsf(x);
    float xc = fminf(fmaxf(x, -9.0f), 9.0f);
    float x2 = __fmul_rn(xc, xc);
    float num = -2.76076847742355e-16f;
    num = __fadd_rn(__fmul_rn(x2, num), 2.00018790482477e-13f);
    num = __fadd_rn(__fmul_rn(x2, num), -8.60467152213735e-11f);
    num = __fadd_rn(__fmul_rn(x2, num), 5.12229709037114e-08f);
    num = __fadd_rn(__fmul_rn(x2, num), 1.48572235717979e-05f);
    num = __fadd_rn(__fmul_rn(x2, num), 6.37261928875436e-04f);
    num = __fadd_rn(__fmul_rn(x2, num), 4.89352455891786e-03f);
    num = __fmul_rn(xc, num);
    float den = 1.19825839466702e-06f;
    den = __fadd_rn(__fmul_rn(x2, den), 1.18534705686654e-04f);
    den = __fadd_rn(__fmul_rn(x2, den), 2.26843463243900e-03f);
    den = __fadd_rn(__fmul_rn(x2, den), 4.89352518554385e-03f);
    float r = __fdiv_rn(num, den);
    return (ax < 0.0004f) ? x : r;
}
__device__ __forceinline__ float xla_sigmoid(float x) {
    return __fadd_rn(0.5f, __fmul_rn(0.5f, xla_fast_tanh(__fmul_rn(0.5f, x))));
}

// ---------------- stage A: pair-split classes, top-2 logit tracking -----
__global__ void __launch_bounds__(256) k_score(
        const float* __restrict__ cls0, const float* __restrict__ cls1,
        const float* __restrict__ cls2, const float* __restrict__ box0,
        const float* __restrict__ box1, const float* __restrict__ box2) {
    int t   = blockIdx.x * 256 + threadIdx.x;
    int g   = t >> 1;               // anchor-group of 4 anchors
    int half = t & 1;               // 0: classes 0-39, 1: classes 40-79
    int b   = blockIdx.y;
    bool wok = (g < NA / 4);
    int gg = wok ? g : (NA / 4 - 1);

    const float4* cp4; const float4* bp4;
    int hw4, W, lp, abase; float sf;
    if (gg < 1600)      { lp = gg;        hw4 = 1600; W = 80; sf = 8.0f;  abase = 0;
                          cp4 = (const float4*)cls0 + (size_t)b * NCLS * 1600;
                          bp4 = (const float4*)box0 + (size_t)b * 4 * 1600; }
    else if (gg < 2000) { lp = gg - 1600; hw4 = 400;  W = 40; sf = 16.0f; abase = 6400;
                          cp4 = (const float4*)cls1 + (size_t)b * NCLS * 400;
                          bp4 = (const float4*)box1 + (size_t)b * 4 * 400; }
    else                { lp = gg - 2000; hw4 = 100;  W = 20; sf = 32.0f; abase = 8000;
                          cp4 = (const float4*)cls2 + (size_t)b * NCLS * 100;
                          bp4 = (const float4*)box2 + (size_t)b * 4 * 100; }

    float best[4], best2[4];
    int   lab[4],  lab2[4];
    #pragma unroll
    for (int j = 0; j < 4; j++) { best[j] = -1e30f; best2[j] = -1e30f; lab[j] = 0; lab2[j] = 0; }

    int c0 = half * 40;
    #pragma unroll 8
    for (int cc = 0; cc < 40; cc++) {
        int c = c0 + cc;
        float4 v = cp4[(size_t)c * hw4 + lp];
        float xs[4] = {v.x, v.y, v.z, v.w};
        #pragma unroll
        for (int j = 0; j < 4; j++) {
            float x = xs[j];
            if (x > best[j])       { best2[j] = best[j]; lab2[j] = lab[j]; best[j] = x; lab[j] = c; }
            else if (x > best2[j]) { best2[j] = x; lab2[j] = c; }
        }
    }

    int base4 = (b * NA + abase) / 4 + lp;

    float ob[4], ob2[4]; int ol[4], ol2[4];
    #pragma unroll
    for (int j = 0; j < 4; j++) {
        ob[j]  = __shfl_xor_sync(0xffffffffu, best[j], 1);
        ob2[j] = __shfl_xor_sync(0xffffffffu, best2[j], 1);
        ol[j]  = __shfl_xor_sync(0xffffffffu, lab[j], 1);
        ol2[j] = __shfl_xor_sync(0xffffffffu, lab2[j], 1);
    }

    if (half == 0 && wok) {
        unsigned key4[4]; unsigned char lab4[4];
        #pragma unroll
        for (int j = 0; j < 4; j++) {
            // merge top-2: even labels (<40) < odd; strict > keeps the
            // smaller label on equal values (first-occurrence).
            float B, S; int BL, SL;
            if (ob[j] > best[j]) {
                B = ob[j]; BL = ol[j];
                if (ob2[j] > best[j]) { S = ob2[j]; SL = ol2[j]; }
                else                  { S = best[j]; SL = lab[j]; }
            } else {
                B = best[j]; BL = lab[j];
                if (ob[j] > best2[j]) { S = ob[j]; SL = ol[j]; }
                else                  { S = best2[j]; SL = lab2[j]; }
            }
            float s1 = xla_sigmoid(B);
            float sc = s1; int lb = BL;
            if (__fsub_rn(B, S) < 1e-3f) {                 // rare near-tie
                float s2 = xla_sigmoid(S);
                if (s2 > s1 || (s2 == s1 && SL < lb)) { sc = s2; lb = SL; }
            }
            float masked = (sc > 0.25f) ? sc : 0.0f;
            key4[j] = __float_as_uint(masked) | 0x80000000u;
            lab4[j] = (unsigned char)lb;
            atomicAdd(&g_hist[b * 1024 + key_bucket(key4[j])], 1);
        }
        ((uint4*)g_key)[base4] = make_uint4(key4[0], key4[1], key4[2], key4[3]);
        *(uchar4*)(g_lab + (size_t)base4 * 4) = make_uchar4(lab4[0], lab4[1], lab4[2], lab4[3]);
    }
    if (half == 1 && wok) {
        float4 d0 = bp4[lp], d1 = bp4[hw4 + lp], d2 = bp4[2 * hw4 + lp], d3 = bp4[3 * hw4 + lp];
        float dd0[4] = {d0.x, d0.y, d0.z, d0.w};
        float dd1[4] = {d1.x, d1.y, d1.z, d1.w};
        float dd2[4] = {d2.x, d2.y, d2.z, d2.w};
        float dd3[4] = {d3.x, d3.y, d3.z, d3.w};
        #pragma unroll
        for (int j = 0; j < 4; j++) {
            int localj = lp * 4 + j;
            float px = __fmul_rn((float)(localj % W), sf);
            float py = __fmul_rn((float)(localj / W), sf);
            float e0 = __fmul_rn(dd0[j], sf);
            float e1 = __fmul_rn(dd1[j], sf);
            float e2 = __fmul_rn(dd2[j], sf);
            float e3 = __fmul_rn(dd3[j], sf);
            g_box[base4 * 4 + j] = make_float4(__fsub_rn(px, e0), __fsub_rn(py, e1),
                                               __fadd_rn(px, e2), __fadd_rn(py, e3));
        }
    }
}

// ---------------- fused stage B+C ---------------------------------------
__global__ void __launch_bounds__(1024) k_sel_nms(float* __restrict__ dout) {
    __shared__ __align__(16) unsigned long long ssort[2048];   // sorted / grp / scan alias
    __shared__ __align__(16) float4 sbox[PRE];                 // also hstart/hcursor
    __shared__ float  sarea[PRE];
    __shared__ int    slist[PRE];
    __shared__ unsigned char ssupp[PRE];
    __shared__ int    swarp[32];
    __shared__ int    sT, sChi, sSv, sMv, sCnt;
    __shared__ int    sstart[NCLS + 1];
    __shared__ int    scnt_[NCLS];
    __shared__ int    soff[NCLS];

    int* sS = (int*)ssort;            // [1024] scan buffer (alias, pre-sort)
    int* h2 = (int*)ssort + 1024;     // [256]  sub-histogram (alias)
    int* hstart  = (int*)sbox;        // [1024] segment starts (from 1st scan)
    int* hcursor = (int*)sbox + 1024; // [1024] scatter cursors

    int b = blockIdx.x, tid = threadIdx.x;
    int wid = tid >> 5, lane = tid & 31;

    // keys resident in registers
    unsigned kreg[9];
    #pragma unroll
    for (int s = 0; s < 9; s++) {
        int i = tid + s * 1024;
        kreg[s] = (i < NA) ? g_key[b * NA + i] : 0u;
    }

    // histogram: load + re-zero for next graph replay
    int hv = g_hist[b * 1024 + tid];
    g_hist[b * 1024 + tid] = 0;
    if (tid == 0) { sT = -1; sChi = 0; sSv = 0; sMv = 0; sCnt = 0; }
    if (tid < NCLS) scnt_[tid] = 0;

    // suffix scan over 1024 buckets: boundary bucket + segment starts
    sS[1023 - tid] = hv;
    __syncthreads();
    {
        int x0 = sS[tid];             // bucket (1023 - tid)
        int x = x0;
        for (int d = 1; d < 32; d <<= 1) {
            int t2 = __shfl_up_sync(0xffffffffu, x, d);
            if (lane >= d) x += t2;
        }
        if (lane == 31) swarp[wid] = x;
        __syncthreads();
        if (wid == 0) {
            int v2 = swarp[lane];
            for (int d = 1; d < 32; d <<= 1) {
                int t2 = __shfl_up_sync(0xffffffffu, v2, d);
                if (lane >= d) v2 += t2;
            }
            swarp[lane] = v2;
        }
        __syncthreads();
        int incl = x + (wid ? swarp[wid - 1] : 0);
        __syncthreads();              // swarp reads done
        sS[tid] = incl;
        hstart[1023 - tid] = incl - x0;   // excl suffix = segment start
        __syncthreads();
        if (incl >= PRE && (tid == 0 || sS[tid - 1] < PRE)) {
            sT = 1023 - tid;
            sChi = tid ? sS[tid - 1] : 0;
        }
        __syncthreads();
    }
    int T = sT, Chi = sChi;
    unsigned v;
    int n = 0;
    bool fastpath = false;

    if (T >= 1 && T <= 1022) {
        // refine within bucket T: 256 sub-buckets of 64 key-values
        if (tid < 256) h2[tid] = 0;
        __syncthreads();
        #pragma unroll
        for (int s = 0; s < 9; s++) {
            unsigned k = kreg[s];
            if (key_bucket(k) == (unsigned)T)
                atomicAdd(&h2[((k - (HBASE + 1u)) >> 6) & 0xFFu], 1);
        }
        __syncthreads();
        // 256-wide suffix scan (warps 0-7)
        int x0 = 0, incl = 0;
        if (tid < 256) x0 = h2[255 - tid];
        int x = x0;
        for (int d = 1; d < 32; d <<= 1) {
            int t2 = __shfl_up_sync(0xffffffffu, x, d);
            if (lane >= d) x += t2;
        }
        if (tid < 256 && lane == 31) swarp[wid] = x;
        __syncthreads();
        if (wid == 0 && lane < 8) {
            int v2 = swarp[lane];
            for (int d = 1; d < 8; d <<= 1) {
                int t2 = __shfl_up_sync(0xFFu, v2, d);
                if (lane >= d) v2 += t2;
            }
            swarp[lane] = v2;
        }
        __syncthreads();
        if (tid < 256) incl = x + (wid ? swarp[wid - 1] : 0);
        __syncthreads();
        if (tid < 256) sS[tid] = incl;
        __syncthreads();
        int m = PRE - Chi;
        if (tid < 256 && incl >= m && (tid == 0 || sS[tid - 1] < m)) {
            sSv = 255 - tid;
            sMv = incl;               // count of keys >= v inside bucket T
        }
        __syncthreads();
        v = (HBASE + 1u) + ((unsigned)(T - 1) << 14) + ((unsigned)sSv << 6);
        n = Chi + sMv;
        fastpath = (n <= 1024);
    } else {
        // rare exact fallback: binary search on register keys
        if (tid < 32) swarp[tid] = 0;
        __syncthreads();
        unsigned lo = 0x80000000u, hi = 0xBF800000u;
        int it = 0;
        while (lo < hi) {
            unsigned mid = lo + ((hi - lo) >> 1) + 1u;
            int c = 0;
            #pragma unroll
            for (int s = 0; s < 9; s++) c += (kreg[s] >= mid);
            for (int d = 16; d; d >>= 1) c += __shfl_down_sync(0xffffffffu, c, d);
            if (lane == 0 && c) atomicAdd(&swarp[it & 31], c);
            __syncthreads();
            int total = swarp[it & 31];
            if (total >= PRE) lo = mid; else hi = mid - 1u;
            it++;
            if ((it & 31) == 0) {
                __syncthreads();
                if (tid < 32) swarp[tid] = 0;
                __syncthreads();
            }
        }
        v = lo;
        fastpath = false;
    }
    __syncthreads();                  // sS/h2 dead -> ssort reusable

    unsigned long long val;
    if (fastpath) {
        // counting sort: cursors from precomputed starts, scatter, rank
        hcursor[tid] = hstart[tid];
        __syncthreads();
        unsigned long long* grp = ssort + 1024;
        #pragma unroll
        for (int s = 0; s < 9; s++) {
            unsigned k = kreg[s];
            if (k >= v) {
                int i = tid + s * 1024;
                unsigned long long pay = ((unsigned long long)k << 32)
                                       | ((unsigned)(8399 - i) << 7)
                                       | (unsigned)g_lab[b * NA + i];
                grp[atomicAdd(&hcursor[(int)key_bucket(k)], 1)] = pay;
            }
        }
        __syncthreads();
        // exact in-segment rank (payloads unique) -> direct placement
        if (tid < n) {
            unsigned long long pay = grp[tid];
            int t = (int)key_bucket((unsigned)(pay >> 32));
            int start = hstart[t], end = hcursor[t];
            int rank = 0;
            for (int g2 = start; g2 < end; g2++) rank += (grp[g2] > pay);
            ssort[start + rank] = pay;
        }
        __syncthreads();
        val = (tid < n) ? ssort[tid] : 0ULL;
    } else {
        // pathological fallback: gather + 2048 bitonic
        #pragma unroll
        for (int s = 0; s < 9; s++) {
            unsigned k = kreg[s];
            if (k >= v) {
                int i = tid + s * 1024;
                int pos = atomicAdd(&sCnt, 1);
                if (pos < 2048)
                    ssort[pos] = ((unsigned long long)k << 32)
                               | ((unsigned)(8399 - i) << 7)
                               | (unsigned)g_lab[b * NA + i];
            }
        }
        __syncthreads();
        int n2 = sCnt; if (n2 > 2048) n2 = 2048;
        for (int i = tid; i < 2048; i += 1024)
            if (i >= n2) ssort[i] = 0ULL;
        __syncthreads();
        for (int k = 2; k <= 2048; k <<= 1) {
            for (int j = k >> 1; j > 0; j >>= 1) {
                for (int i = tid; i < 2048; i += 1024) {
                    int ixj = i ^ j;
                    if (ixj > i) {
                        unsigned long long x = ssort[i], y = ssort[ixj];
                        bool desc = ((i & k) == 0);
                        if ((x < y) == desc) { ssort[i] = y; ssort[ixj] = x; }
                    }
                }
                __syncthreads();
            }
        }
        val = ssort[tid];
        __syncthreads();
    }

    // decode own candidate; count classes via one atomic each
    // (sbox region: hstart/hcursor dead from here)
    float4 myraw = make_float4(0, 0, 0, 0);
    float  mysc = 0.0f; int mylab = 0;
    if (tid < PRE) {
        unsigned low = (unsigned)val;
        mylab = (int)(low & 0x7Fu);
        int idx = 8399 - (int)((low >> 7) & 0x3FFFu);
        mysc = __uint_as_float((unsigned)(val >> 32) & 0x7FFFFFFFu);
        myraw = g_box[b * NA + idx];
    }
    __syncthreads();                  // all hstart/hcursor reads complete
    if (tid < PRE) {
        float off = __fmul_rn((float)mylab, 8192.0f);
        float4 myoff = make_float4(__fadd_rn(myraw.x, off), __fadd_rn(myraw.y, off),
                                   __fadd_rn(myraw.z, off), __fadd_rn(myraw.w, off));
        float myarea = __fmul_rn(fmaxf(__fsub_rn(myoff.z, myoff.x), 0.0f),
                                 fmaxf(__fsub_rn(myoff.w, myoff.y), 0.0f));
        sbox[tid]   = myoff;
        sarea[tid]  = myarea;
        ssupp[tid]  = (mysc > 0.25f) ? 0 : 1;   // invalid = pre-suppressed
        atomicAdd(&scnt_[mylab], 1);
    }
    __syncthreads();

    // exclusive prefix over 80 class counts: warp 0 shfl-scan, 3 chunks
    if (wid == 0) {
        int carry = 0;
        #pragma unroll
        for (int chunk = 0; chunk < 3; chunk++) {
            int ci = chunk * 32 + lane;
            int x0 = (ci < NCLS) ? scnt_[ci] : 0;
            int x = x0;
            for (int d = 1; d < 32; d <<= 1) {
                int tt = __shfl_up_sync(0xffffffffu, x, d);
                if (lane >= d) x += tt;
            }
            if (ci < NCLS) sstart[ci] = carry + x - x0;
            carry += __shfl_sync(0xffffffffu, x, 31);
        }
        if (lane == 0) sstart[NCLS] = carry;
    }
    __syncthreads();
    if (tid < NCLS) soff[tid] = sstart[tid];
    __syncthreads();

    // unordered scatter, then per-warp class-segment sort (positions asc)
    if (tid < PRE) slist[atomicAdd(&soff[mylab], 1)] = tid;
    __syncthreads();

    for (int c = wid; c < NCLS; c += 32) {
        int st = sstart[c], ni = sstart[c + 1] - st;
        if (ni > 1) {
            if (ni <= 32) {
                unsigned vv = (lane < ni) ? ~(unsigned)slist[st + lane] : 0u;
                #pragma unroll
                for (int k = 2; k <= 32; k <<= 1) {
                    #pragma unroll
                    for (int j = k >> 1; j > 0; j >>= 1) {
                        unsigned p = __shfl_xor_sync(0xffffffffu, vv, j);
                        bool keep_max = ((lane & j) == 0) != ((lane & k) != 0);
                        if (keep_max == (p > vv)) vv = p;
                    }
                }
                if (lane < ni) slist[st + lane] = (int)~vv;
            } else if (lane == 0) {
                for (int a2 = st + 1; a2 < st + ni; a2++) {
                    int x = slist[a2]; int bq = a2 - 1;
                    while (bq >= st && slist[bq] > x) { slist[bq + 1] = slist[bq]; bq--; }
                    slist[bq + 1] = x;
                }
            }
        }
        __syncwarp();
    }
    __syncthreads();

    // 8-lane sub-warp group per class: all 80 classes run concurrently.
    // greedy NMS, reference-exact IoU; cross-class IoU exactly 0.
    {
        int gidx  = tid >> 3;                       // group id, 0..127
        int glane = tid & 7;
        unsigned gmask = 0xFFu << (lane & 24);      // this group's lanes in warp
        if (gidx < NCLS) {
            int c = gidx;
            int st = sstart[c], ni = sstart[c + 1] - st;
            for (int ii = 0; ii < ni; ii++) {
                __syncwarp(gmask);
                int idx_i = slist[st + ii];
                if (ssupp[idx_i]) continue;         // uniform within group
                float4 bi = sbox[idx_i];
                float  ai = sarea[idx_i];
                for (int jj = ii + 1 + glane; jj < ni; jj += 8) {
                    int idx_j = slist[st + jj];
                    float4 bj = sbox[idx_j];
                    float ltx = fmaxf(bi.x, bj.x), lty = fmaxf(bi.y, bj.y);
                    float rbx = fminf(bi.z, bj.z), rby = fminf(bi.w, bj.w);
                    float w = fmaxf(__fsub_rn(rbx, ltx), 0.0f);
                    float h = fmaxf(__fsub_rn(rby, lty), 0.0f);
                    float inter = __fmul_rn(w, h);
                    float den = fmaxf(__fsub_rn(__fadd_rn(ai, sarea[idx_j]), inter), 1e-6f);
                    if (__fdiv_rn(inter, den) > 0.65f) ssupp[idx_j] = 1;
                }
            }
        }
    }
    __syncthreads();

    // emit: kept entries keep sorted order; zero-score fills index-ascending
    bool keep = (tid < PRE) ? (ssupp[tid] == 0) : false;
    unsigned bal = __ballot_sync(0xffffffffu, keep);
    int before_in_warp = __popc(bal & ((1u << lane) - 1u));
    if (lane == 0) swarp[wid] = __popc(bal);
    __syncthreads();
    if (tid < 32) {
        int vv = swarp[tid];
        for (int d = 1; d < 32; d <<= 1) {
            int tt = __shfl_up_sync(0xffffffffu, vv, d);
            if (lane >= d) vv += tt;
        }
        swarp[tid] = vv;
    }
    __syncthreads();
    int rank = ((wid == 0) ? 0 : swarp[wid - 1]) + before_in_warp;
    int K = swarp[31];

    if (tid < PRE) {
        int slot = keep ? rank : (K + (tid - rank));
        if (slot < KEEP) {
            float* dd = dout + (size_t)b * KEEP * 5 + (size_t)slot * 5;
            float sc = keep ? mysc : 0.0f;
            dd[0] = myraw.x; dd[1] = myraw.y; dd[2] = myraw.z; dd[3] = myraw.w; dd[4] = sc;
            dout[(size_t)NB * KEEP * 5 + b * KEEP + slot] = (float)mylab;
        }
    }
}

extern "C" void kernel_launch(void* const* d_in, const int* in_sizes, int n_in,
                              void* d_out, int out_size) {
    const float* cls0 = (const float*)d_in[0];
    const float* cls1 = (const float*)d_in[1];
    const float* cls2 = (const float*)d_in[2];
    const float* box0 = (const float*)d_in[3];
    const float* box1 = (const float*)d_in[4];
    const float* box2 = (const float*)d_in[5];
    float* out = (float*)d_out;

    dim3 gA((NA / 4 * 2 + 255) / 256, NB);
    k_score<<<gA, 256>>>(cls0, cls1, cls2, box0, box1, box2);
    k_sel_nms<<<NB, 1024>>>(out);
}

// round 16
// speedup vs baseline: 2.1394x; 1.1086x over previous
#include <cuda_runtime.h>
#include <cuda_bf16.h>

#define NB   16
#define NA   8400
#define NCLS 80
#define PRE  1000
#define KEEP 100
#define NCAP 1536           // counting-sort capacity
#define HBASE 0xBE800000u   // key base for score==0.25; valid keys are > this

// ---------------- global scratch ----------------------------------------
static __device__ float4             g_box[NB * NA];
static __device__ unsigned long long g_pay[NB * NA];   // key<<32 | (8399-i)<<7 | lab
static __device__ int                g_hist[NB * 1024]; // zero-init; k_sel re-zeros

// key -> monotone bucket in [0,1023]
__device__ __forceinline__ unsigned key_bucket(unsigned k) {
    if (k <= HBASE) return 0u;
    unsigned u = (k - (HBASE + 1u)) >> 14;
    return 1u + (u > 1022u ? 1022u : u);
}

// ---------------- XLA-exact sigmoid -------------------------------------
// XLA logistic expander: logistic(x) = 0.5 + 0.5 * tanh(0.5 * x)
// XLA fast-tanh: clamp [-9,9], rational poly, identity for |x| < 0.0004.
__device__ __forceinline__ float xla_fast_tanh(float x) {
    float ax = fabsf(x);
    float xc = fminf(fmaxf(x, -9.0f), 9.0f);
    float x2 = __fmul_rn(xc, xc);
    float num = -2.76076847742355e-16f;
    num = __fadd_rn(__fmul_rn(x2, num), 2.00018790482477e-13f);
    num = __fadd_rn(__fmul_rn(x2, num), -8.60467152213735e-11f);
    num = __fadd_rn(__fmul_rn(x2, num), 5.12229709037114e-08f);
    num = __fadd_rn(__fmul_rn(x2, num), 1.48572235717979e-05f);
    num = __fadd_rn(__fmul_rn(x2, num), 6.37261928875436e-04f);
    num = __fadd_rn(__fmul_rn(x2, num), 4.89352455891786e-03f);
    num = __fmul_rn(xc, num);
    float den = 1.19825839466702e-06f;
    den = __fadd_rn(__fmul_rn(x2, den), 1.18534705686654e-04f);
    den = __fadd_rn(__fmul_rn(x2, den), 2.26843463243900e-03f);
    den = __fadd_rn(__fmul_rn(x2, den), 4.89352518554385e-03f);
    float r = __fdiv_rn(num, den);
    return (ax < 0.0004f) ? x : r;
}
__device__ __forceinline__ float xla_sigmoid(float x) {
    return __fadd_rn(0.5f, __fmul_rn(0.5f, xla_fast_tanh(__fmul_rn(0.5f, x))));
}

// merge other's top-2 into own; REQUIRES other's labels all > own's labels
// so strict > keeps the smaller label on equal values (first-occurrence).
__device__ __forceinline__ void merge2(float& B, float& S, int& BL, int& SL,
                                       float oB, float oS, int oBL, int oSL) {
    if (oB > B) {
        if (oS > B) { S = oS; SL = oSL; }
        else        { S = B;  SL = BL;  }
        B = oB; BL = oBL;
    } else {
        if (oB > S) { S = oB; SL = oBL; }
    }
}

// ---------------- stage A: 4-way class split, top-2 logit tracking ------
// Thread quad splits 80 classes 20/20/20/20; two shfl merge levels.
// Only quarters 0/2's level-1 merges and quarter 0's level-2 merge are
// consumed, and for those "other" labels are strictly larger -> exact
// first-occurrence tie semantics.  max(sigmoid)=sigmoid(max logit) unless
// runner-up within 1e-3 (then both sigmoids + reference tie-break).
__global__ void __launch_bounds__(256) k_score(
        const float* __restrict__ cls0, const float* __restrict__ cls1,
        const float* __restrict__ cls2, const float* __restrict__ box0,
        const float* __restrict__ box1, const float* __restrict__ box2) {
    int t = blockIdx.x * 256 + threadIdx.x;
    int g = t >> 2;                 // anchor-group of 4 anchors
    int q = t & 3;                  // class quarter
    int b = blockIdx.y;
    bool wok = (g < NA / 4);
    int gg = wok ? g : (NA / 4 - 1);

    const float4* cp4; const float4* bp4;
    int hw4, W, lp, abase; float sf;
    if (gg < 1600)      { lp = gg;        hw4 = 1600; W = 80; sf = 8.0f;  abase = 0;
                          cp4 = (const float4*)cls0 + (size_t)b * NCLS * 1600;
                          bp4 = (const float4*)box0 + (size_t)b * 4 * 1600; }
    else if (gg < 2000) { lp = gg - 1600; hw4 = 400;  W = 40; sf = 16.0f; abase = 6400;
                          cp4 = (const float4*)cls1 + (size_t)b * NCLS * 400;
                          bp4 = (const float4*)box1 + (size_t)b * 4 * 400; }
    else                { lp = gg - 2000; hw4 = 100;  W = 20; sf = 32.0f; abase = 8000;
                          cp4 = (const float4*)cls2 + (size_t)b * NCLS * 100;
                          bp4 = (const float4*)box2 + (size_t)b * 4 * 100; }

    float best[4], best2[4];
    int   lab[4],  lab2[4];
    #pragma unroll
    for (int j = 0; j < 4; j++) { best[j] = -1e30f; best2[j] = -1e30f; lab[j] = 0; lab2[j] = 0; }

    int c0 = q * 20;
    #pragma unroll 10
    for (int cc = 0; cc < 20; cc++) {
        int c = c0 + cc;
        float4 v = cp4[(size_t)c * hw4 + lp];
        float xs[4] = {v.x, v.y, v.z, v.w};
        #pragma unroll
        for (int j = 0; j < 4; j++) {
            float x = xs[j];
            if (x > best[j])       { best2[j] = best[j]; lab2[j] = lab[j]; best[j] = x; lab[j] = c; }
            else if (x > best2[j]) { best2[j] = x; lab2[j] = c; }
        }
    }

    // two-level shfl merge: xor 1, then xor 2
    #pragma unroll
    for (int lvl = 1; lvl <= 2; lvl <<= 1) {
        #pragma unroll
        for (int j = 0; j < 4; j++) {
            float oB  = __shfl_xor_sync(0xffffffffu, best[j], lvl);
            float oS  = __shfl_xor_sync(0xffffffffu, best2[j], lvl);
            int   oBL = __shfl_xor_sync(0xffffffffu, lab[j], lvl);
            int   oSL = __shfl_xor_sync(0xffffffffu, lab2[j], lvl);
            merge2(best[j], best2[j], lab[j], lab2[j], oB, oS, oBL, oSL);
        }
    }

    int base4 = (b * NA + abase) / 4 + lp;

    if (q == 0 && wok) {
        unsigned long long pay[4];
        #pragma unroll
        for (int j = 0; j < 4; j++) {
            float s1 = xla_sigmoid(best[j]);
            float sc = s1; int lb = lab[j];
            if (__fsub_rn(best[j], best2[j]) < 1e-3f) {    // rare near-tie
                float s2 = xla_sigmoid(best2[j]);
                if (s2 > s1 || (s2 == s1 && lab2[j] < lb)) { sc = s2; lb = lab2[j]; }
            }
            float masked = (sc > 0.25f) ? sc : 0.0f;
            unsigned key = __float_as_uint(masked) | 0x80000000u;
            int i = abase + lp * 4 + j;                    // global anchor idx
            pay[j] = ((unsigned long long)key << 32)
                   | ((unsigned)(8399 - i) << 7) | (unsigned)lb;
            atomicAdd(&g_hist[b * 1024 + key_bucket(key)], 1);
        }
        unsigned long long* dst = g_pay + (size_t)base4 * 4;
        ((ulonglong2*)dst)[0] = make_ulonglong2(pay[0], pay[1]);
        ((ulonglong2*)dst)[1] = make_ulonglong2(pay[2], pay[3]);
    }
    if (q == 1 && wok) {
        float4 d0 = bp4[lp], d1 = bp4[hw4 + lp], d2 = bp4[2 * hw4 + lp], d3 = bp4[3 * hw4 + lp];
        float dd0[4] = {d0.x, d0.y, d0.z, d0.w};
        float dd1[4] = {d1.x, d1.y, d1.z, d1.w};
        float dd2[4] = {d2.x, d2.y, d2.z, d2.w};
        float dd3[4] = {d3.x, d3.y, d3.z, d3.w};
        #pragma unroll
        for (int j = 0; j < 4; j++) {
            int localj = lp * 4 + j;
            float px = __fmul_rn((float)(localj % W), sf);
            float py = __fmul_rn((float)(localj / W), sf);
            float e0 = __fmul_rn(dd0[j], sf);
            float e1 = __fmul_rn(dd1[j], sf);
            float e2 = __fmul_rn(dd2[j], sf);
            float e3 = __fmul_rn(dd3[j], sf);
            g_box[base4 * 4 + j] = make_float4(__fsub_rn(px, e0), __fsub_rn(py, e1),
                                               __fadd_rn(px, e2), __fadd_rn(py, e3));
        }
    }
}

// ---------------- fused stage B+C ---------------------------------------
__global__ void __launch_bounds__(1024) k_sel_nms(float* __restrict__ dout) {
    __shared__ __align__(16) char pool[40960];
    int* sS      = (int*)pool;                               // [1024] scan
    int* hstart  = (int*)(pool + 4096);                      // [1024] seg starts
    int* hcursor = (int*)(pool + 8192);                      // [1024] cursors
    unsigned long long* grp   = (unsigned long long*)(pool + 16384);  // [1536]
    unsigned long long* out   = (unsigned long long*)(pool + 28672);  // [1536]
    unsigned long long* sfall = (unsigned long long*)pool;            // [2048] fallback
    float4*        sbox  = (float4*)pool;                    // [1000] phase C
    float*         sarea = (float*)(pool + 16384);
    int*           slist = (int*)(pool + 20480);
    unsigned char* ssupp = (unsigned char*)(pool + 24576);

    __shared__ int swarp[32];
    __shared__ int sT, sN0, sCnt;
    __shared__ int sstart[NCLS + 1];
    __shared__ int scnt_[NCLS];
    __shared__ int soff[NCLS];

    int b = blockIdx.x, tid = threadIdx.x;
    int wid = tid >> 5, lane = tid & 31;

    // payloads resident in registers (coalesced u64 loads)
    unsigned long long kreg[9];
    #pragma unroll
    for (int s = 0; s < 9; s++) {
        int i = tid + s * 1024;
        kreg[s] = (i < NA) ? g_pay[b * NA + i] : 0ULL;
    }

    // histogram: load + re-zero for next graph replay
    int hv = g_hist[b * 1024 + tid];
    g_hist[b * 1024 + tid] = 0;
    if (tid == 0) { sT = -1; sN0 = 0; sCnt = 0; }
    if (tid < NCLS) scnt_[tid] = 0;

    // suffix scan over 1024 buckets: boundary bucket + segment starts
    sS[1023 - tid] = hv;
    __syncthreads();
    {
        int x0 = sS[tid];             // bucket (1023 - tid)
        int x = x0;
        for (int d = 1; d < 32; d <<= 1) {
            int t2 = __shfl_up_sync(0xffffffffu, x, d);
            if (lane >= d) x += t2;
        }
        if (lane == 31) swarp[wid] = x;
        __syncthreads();
        if (wid == 0) {
            int v2 = swarp[lane];
            for (int d = 1; d < 32; d <<= 1) {
                int t2 = __shfl_up_sync(0xffffffffu, v2, d);
                if (lane >= d) v2 += t2;
            }
            swarp[lane] = v2;
        }
        __syncthreads();
        int incl = x + (wid ? swarp[wid - 1] : 0);
        __syncthreads();              // swarp reads done before reuse
        sS[tid] = incl;
        hstart[1023 - tid] = incl - x0;   // excl suffix = segment start
        __syncthreads();
        if (incl >= PRE && (tid == 0 || sS[tid - 1] < PRE)) {
            sT = 1023 - tid;
            sN0 = incl;               // candidates at bucket granularity
        }
        __syncthreads();
    }
    int T = sT, n = sN0;
    bool fast = (T >= 1 && n <= NCAP);
    unsigned long long val = 0ULL;

    if (fast) {
        // v = lower edge of boundary bucket; counting sort at bucket grain
        unsigned v = (T <= 1022) ? (HBASE + 1u) + ((unsigned)(T - 1) << 14)
                                 : (HBASE + 1u) + (1022u << 14);
        hcursor[tid] = hstart[tid];
        __syncthreads();
        #pragma unroll
        for (int s = 0; s < 9; s++) {
            unsigned long long pay = kreg[s];
            unsigned k = (unsigned)(pay >> 32);
            if (k >= v)
                grp[atomicAdd(&hcursor[(int)key_bucket(k)], 1)] = pay;
        }
        __syncthreads();
        // exact in-segment rank (payloads unique) -> direct placement
        for (int e = tid; e < n; e += 1024) {
            unsigned long long pay = grp[e];
            int t = (int)key_bucket((unsigned)(pay >> 32));
            int start = hstart[t], end = hcursor[t];
            int rank = 0;
            for (int g2 = start; g2 < end; g2++) rank += (grp[g2] > pay);
            out[start + rank] = pay;
        }
        __syncthreads();
        if (tid < PRE) val = out[tid];
    } else {
        // rare: exact binary-search threshold + gather + 2048 bitonic
        if (tid < 32) swarp[tid] = 0;
        __syncthreads();
        unsigned lo = 0x80000000u, hi = 0xBF800000u;
        int it = 0;
        while (lo < hi) {
            unsigned mid = lo + ((hi - lo) >> 1) + 1u;
            int c = 0;
            #pragma unroll
            for (int s = 0; s < 9; s++) c += ((unsigned)(kreg[s] >> 32) >= mid);
            for (int d = 16; d; d >>= 1) c += __shfl_down_sync(0xffffffffu, c, d);
            if (lane == 0 && c) atomicAdd(&swarp[it & 31], c);
            __syncthreads();
            int total = swarp[it & 31];
            if (total >= PRE) lo = mid; else hi = mid - 1u;
            it++;
            if ((it & 31) == 0) {
                __syncthreads();
                if (tid < 32) swarp[tid] = 0;
                __syncthreads();
            }
        }
        unsigned v = lo;
        __syncthreads();              // scan arrays dead -> sfall reusable
        #pragma unroll
        for (int s = 0; s < 9; s++) {
            unsigned long long pay = kreg[s];
            if ((unsigned)(pay >> 32) >= v) {
                int pos = atomicAdd(&sCnt, 1);
                if (pos < 2048) sfall[pos] = pay;
            }
        }
        __syncthreads();
        int n2 = sCnt; if (n2 > 2048) n2 = 2048;
        for (int i = tid; i < 2048; i += 1024)
            if (i >= n2) sfall[i] = 0ULL;
        __syncthreads();
        for (int k = 2; k <= 2048; k <<= 1) {
            for (int j = k >> 1; j > 0; j >>= 1) {
                for (int i = tid; i < 2048; i += 1024) {
                    int ixj = i ^ j;
                    if (ixj > i) {
                        unsigned long long x = sfall[i], y = sfall[ixj];
                        bool desc = ((i & k) == 0);
                        if ((x < y) == desc) { sfall[i] = y; sfall[ixj] = x; }
                    }
                }
                __syncthreads();
            }
        }
        val = sfall[tid];
    }

    // decode own candidate (score from key bits; one scattered box load)
    float4 myraw = make_float4(0, 0, 0, 0);
    float  mysc = 0.0f; int mylab = 0;
    if (tid < PRE) {
        unsigned low = (unsigned)val;
        mylab = (int)(low & 0x7Fu);
        int idx = 8399 - (int)((low >> 7) & 0x3FFFu);
        mysc = __uint_as_float((unsigned)(val >> 32) & 0x7FFFFFFFu);
        myraw = g_box[b * NA + idx];
    }
    __syncthreads();                  // all pool reads complete -> phase C
    if (tid < PRE) {
        float off = __fmul_rn((float)mylab, 8192.0f);
        float4 myoff = make_float4(__fadd_rn(myraw.x, off), __fadd_rn(myraw.y, off),
                                   __fadd_rn(myraw.z, off), __fadd_rn(myraw.w, off));
        float myarea = __fmul_rn(fmaxf(__fsub_rn(myoff.z, myoff.x), 0.0f),
                                 fmaxf(__fsub_rn(myoff.w, myoff.y), 0.0f));
        sbox[tid]   = myoff;
        sarea[tid]  = myarea;
        ssupp[tid]  = (mysc > 0.25f) ? 0 : 1;   // invalid = pre-suppressed
        atomicAdd(&scnt_[mylab], 1);
    }
    __syncthreads();

    // exclusive prefix over 80 class counts: warp 0 shfl-scan, 3 chunks
    if (wid == 0) {
        int carry = 0;
        #pragma unroll
        for (int chunk = 0; chunk < 3; chunk++) {
            int ci = chunk * 32 + lane;
            int x0 = (ci < NCLS) ? scnt_[ci] : 0;
            int x = x0;
            for (int d = 1; d < 32; d <<= 1) {
                int tt = __shfl_up_sync(0xffffffffu, x, d);
                if (lane >= d) x += tt;
            }
            if (ci < NCLS) sstart[ci] = carry + x - x0;
            carry += __shfl_sync(0xffffffffu, x, 31);
        }
        if (lane == 0) sstart[NCLS] = carry;
    }
    __syncthreads();
    if (tid < NCLS) soff[tid] = sstart[tid];
    __syncthreads();

    // unordered scatter, then per-warp class-segment sort (positions asc)
    if (tid < PRE) slist[atomicAdd(&soff[mylab], 1)] = tid;
    __syncthreads();

    for (int c = wid; c < NCLS; c += 32) {
        int st = sstart[c], ni = sstart[c + 1] - st;
        if (ni > 1) {
            if (ni <= 32) {
                unsigned vv = (lane < ni) ? ~(unsigned)slist[st + lane] : 0u;
                #pragma unroll
                for (int k = 2; k <= 32; k <<= 1) {
                    #pragma unroll
                    for (int j = k >> 1; j > 0; j >>= 1) {
                        unsigned p = __shfl_xor_sync(0xffffffffu, vv, j);
                        bool keep_max = ((lane & j) == 0) != ((lane & k) != 0);
                        if (keep_max == (p > vv)) vv = p;
                    }
                }
                if (lane < ni) slist[st + lane] = (int)~vv;
            } else if (lane == 0) {
                for (int a2 = st + 1; a2 < st + ni; a2++) {
                    int x = slist[a2]; int bq = a2 - 1;
                    while (bq >= st && slist[bq] > x) { slist[bq + 1] = slist[bq]; bq--; }
                    slist[bq + 1] = x;
                }
            }
        }
        __syncwarp();
    }
    __syncthreads();

    // 8-lane sub-warp group per class: all 80 classes run concurrently.
    // greedy NMS, reference-exact IoU; cross-class IoU exactly 0.
    {
        int gidx  = tid >> 3;                       // group id, 0..127
        int glane = tid & 7;
        unsigned gmask = 0xFFu << (lane & 24);      // this group's lanes in warp
        if (gidx < NCLS) {
            int c = gidx;
            int st = sstart[c], ni = sstart[c + 1] - st;
            for (int ii = 0; ii < ni; ii++) {
                __syncwarp(gmask);
                int idx_i = slist[st + ii];
                if (ssupp[idx_i]) continue;         // uniform within group
                float4 bi = sbox[idx_i];
                float  ai = sarea[idx_i];
                for (int jj = ii + 1 + glane; jj < ni; jj += 8) {
                    int idx_j = slist[st + jj];
                    float4 bj = sbox[idx_j];
                    float ltx = fmaxf(bi.x, bj.x), lty = fmaxf(bi.y, bj.y);
                    float rbx = fminf(bi.z, bj.z), rby = fminf(bi.w, bj.w);
                    float w = fmaxf(__fsub_rn(rbx, ltx), 0.0f);
                    float h = fmaxf(__fsub_rn(rby, lty), 0.0f);
                    float inter = __fmul_rn(w, h);
                    float den = fmaxf(__fsub_rn(__fadd_rn(ai, sarea[idx_j]), inter), 1e-6f);
                    if (__fdiv_rn(inter, den) > 0.65f) ssupp[idx_j] = 1;
                }
            }
        }
    }
    __syncthreads();

    // emit: kept entries keep sorted order; zero-score fills index-ascending
    bool keep = (tid < PRE) ? (ssupp[tid] == 0) : false;
    unsigned bal = __ballot_sync(0xffffffffu, keep);
    int before_in_warp = __popc(bal & ((1u << lane) - 1u));
    if (lane == 0) swarp[wid] = __popc(bal);
    __syncthreads();
    if (tid < 32) {
        int vv = swarp[tid];
        for (int d = 1; d < 32; d <<= 1) {
            int tt = __shfl_up_sync(0xffffffffu, vv, d);
            if (lane >= d) vv += tt;
        }
        swarp[tid] = vv;
    }
    __syncthreads();
    int rank = ((wid == 0) ? 0 : swarp[wid - 1]) + before_in_warp;
    int K = swarp[31];

    if (tid < PRE) {
        int slot = keep ? rank : (K + (tid - rank));
        if (slot < KEEP) {
            float* dd = dout + (size_t)b * KEEP * 5 + (size_t)slot * 5;
            float sc = keep ? mysc : 0.0f;
            dd[0] = myraw.x; dd[1] = myraw.y; dd[2] = myraw.z; dd[3] = myraw.w; dd[4] = sc;
            dout[(size_t)NB * KEEP * 5 + b * KEEP + slot] = (float)mylab;
        }
    }
}

extern "C" void kernel_launch(void* const* d_in, const int* in_sizes, int n_in,
                              void* d_out, int out_size) {
    const float* cls0 = (const float*)d_in[0];
    const float* cls1 = (const float*)d_in[1];
    const float* cls2 = (const float*)d_in[2];
    const float* box0 = (const float*)d_in[3];
    const float* box1 = (const float*)d_in[4];
    const float* box2 = (const float*)d_in[5];
    float* out = (float*)d_out;

    dim3 gA((NA / 4 * 4 + 255) / 256, NB);   // 33 x 16 blocks, thread-quads
    k_score<<<gA, 256>>>(cls0, cls1, cls2, box0, box1, box2);
    k_sel_nms<<<NB, 1024>>>(out);
}